// round 12
// baseline (speedup 1.0000x reference)
#include <cuda_runtime.h>
#include <cuda_bf16.h>
#include <cstdint>

#define QL   1024
#define BSZ  4
#define DM   1024
#define NH   16
#define DH   64
#define HD   1024      // NH*DH
#define QKV3 3072
#define NROWS (QL*BSZ) // 4096
#define ATT_SCALE 0.125f

// ---------------- scratch (no allocation allowed) ----------------
__device__ __align__(16) float g_ao[(size_t)NROWS * DM];

// split-bf16 GEMM operands
__device__ __align__(16) __nv_bfloat16 g_w_hi[(size_t)NROWS * DM];
__device__ __align__(16) __nv_bfloat16 g_w_lo[(size_t)NROWS * DM];
__device__ __align__(16) __nv_bfloat16 g_r_hi[(size_t)QL * DM];
__device__ __align__(16) __nv_bfloat16 g_r_lo[(size_t)QL * DM];
__device__ __align__(16) __nv_bfloat16 g_vec_hi[(size_t)NROWS * HD];
__device__ __align__(16) __nv_bfloat16 g_vec_lo[(size_t)NROWS * HD];
__device__ __align__(16) __nv_bfloat16 g_qkvwT_hi[(size_t)QKV3 * DM];
__device__ __align__(16) __nv_bfloat16 g_qkvwT_lo[(size_t)QKV3 * DM];
__device__ __align__(16) __nv_bfloat16 g_rkwT_hi[(size_t)HD * DM];
__device__ __align__(16) __nv_bfloat16 g_rkwT_lo[(size_t)HD * DM];
__device__ __align__(16) __nv_bfloat16 g_owT_hi[(size_t)DM * HD];
__device__ __align__(16) __nv_bfloat16 g_owT_lo[(size_t)DM * HD];

// attention repacked operands: [b][n][row][64] bf16 (written by GEMM epilogues)
__device__ __align__(16) __nv_bfloat16 g_QWh[(size_t)NROWS * HD];
__device__ __align__(16) __nv_bfloat16 g_QWl[(size_t)NROWS * HD];
__device__ __align__(16) __nv_bfloat16 g_QRh[(size_t)NROWS * HD];
__device__ __align__(16) __nv_bfloat16 g_QRl[(size_t)NROWS * HD];
__device__ __align__(16) __nv_bfloat16 g_Kph[(size_t)NROWS * HD];
__device__ __align__(16) __nv_bfloat16 g_Kpl[(size_t)NROWS * HD];
__device__ __align__(16) __nv_bfloat16 g_Vph[(size_t)NROWS * HD];
__device__ __align__(16) __nv_bfloat16 g_Vpl[(size_t)NROWS * HD];
__device__ __align__(16) __nv_bfloat16 g_Rph[(size_t)NH * QL * DH];
__device__ __align__(16) __nv_bfloat16 g_Rpl[(size_t)NH * QL * DH];

// ---------------- PTX helpers ----------------
__device__ __forceinline__ uint32_t smem_u32(const void* p) {
    uint32_t a;
    asm("{ .reg .u64 t; cvta.to.shared.u64 t, %1; cvt.u32.u64 %0, t; }" : "=r"(a) : "l"(p));
    return a;
}
__device__ __forceinline__ void cp16(uint32_t s, const void* g) {
    asm volatile("cp.async.cg.shared.global [%0], [%1], 16;" :: "r"(s), "l"(g));
}
__device__ __forceinline__ void cp_commit() {
    asm volatile("cp.async.commit_group;" ::: "memory");
}
__device__ __forceinline__ void cp_wait0() {
    asm volatile("cp.async.wait_group 0;" ::: "memory");
}
__device__ __forceinline__ void cp_wait1() {
    asm volatile("cp.async.wait_group 1;" ::: "memory");
}
__device__ __forceinline__ void ldsm4(uint32_t& r0, uint32_t& r1, uint32_t& r2, uint32_t& r3,
                                      uint32_t a) {
    asm volatile("ldmatrix.sync.aligned.m8n8.x4.shared.b16 {%0,%1,%2,%3}, [%4];"
                 : "=r"(r0), "=r"(r1), "=r"(r2), "=r"(r3) : "r"(a));
}
__device__ __forceinline__ void ldsm4t(uint32_t& r0, uint32_t& r1, uint32_t& r2, uint32_t& r3,
                                       uint32_t a) {
    asm volatile("ldmatrix.sync.aligned.m8n8.x4.trans.shared.b16 {%0,%1,%2,%3}, [%4];"
                 : "=r"(r0), "=r"(r1), "=r"(r2), "=r"(r3) : "r"(a));
}
__device__ __forceinline__ void mma16816(float* d, const uint32_t* a, const uint32_t* b) {
    asm volatile("mma.sync.aligned.m16n8k16.row.col.f32.bf16.bf16.f32 "
                 "{%0,%1,%2,%3}, {%4,%5,%6,%7}, {%8,%9}, {%0,%1,%2,%3};"
                 : "+f"(d[0]), "+f"(d[1]), "+f"(d[2]), "+f"(d[3])
                 : "r"(a[0]), "r"(a[1]), "r"(a[2]), "r"(a[3]), "r"(b[0]), "r"(b[1]));
}
__device__ __forceinline__ uint32_t packbf(float a, float b) {
    __nv_bfloat162 t = __halves2bfloat162(__float2bfloat16(a), __float2bfloat16(b));
    uint32_t u;
    *(__nv_bfloat162*)&u = t;
    return u;
}
__device__ __forceinline__ void split2(__nv_bfloat16* hi, __nv_bfloat16* lo, float a, float b) {
    __nv_bfloat16 h0 = __float2bfloat16(a), h1 = __float2bfloat16(b);
    *(__nv_bfloat162*)hi = __halves2bfloat162(h0, h1);
    *(__nv_bfloat162*)lo = __halves2bfloat162(
        __float2bfloat16(a - __bfloat162float(h0)),
        __float2bfloat16(b - __bfloat162float(h1)));
}

// swizzled byte offset for [rows][64 bf16] tiles (128B rows)
#define ASWZ(row, ch) ((uint32_t)((row) * 128 + ((((ch) ^ ((row) & 7))) << 4)))

// ---------------- split / transpose-split conversion kernels ----------------
__global__ __launch_bounds__(256) void split_kernel(
    const float4* __restrict__ x, __nv_bfloat162* __restrict__ hi,
    __nv_bfloat162* __restrict__ lo, int n4)
{
    int i = blockIdx.x * 256 + threadIdx.x;
    if (i >= n4) return;
    float4 v = x[i];
    __nv_bfloat16 h0 = __float2bfloat16(v.x);
    __nv_bfloat16 h1 = __float2bfloat16(v.y);
    __nv_bfloat16 h2 = __float2bfloat16(v.z);
    __nv_bfloat16 h3 = __float2bfloat16(v.w);
    __nv_bfloat16 l0 = __float2bfloat16(v.x - __bfloat162float(h0));
    __nv_bfloat16 l1 = __float2bfloat16(v.y - __bfloat162float(h1));
    __nv_bfloat16 l2 = __float2bfloat16(v.z - __bfloat162float(h2));
    __nv_bfloat16 l3 = __float2bfloat16(v.w - __bfloat162float(h3));
    hi[2 * i]     = __halves2bfloat162(h0, h1);
    hi[2 * i + 1] = __halves2bfloat162(h2, h3);
    lo[2 * i]     = __halves2bfloat162(l0, l1);
    lo[2 * i + 1] = __halves2bfloat162(l2, l3);
}

__global__ __launch_bounds__(256) void transpose_split_kernel(
    const float* __restrict__ W, __nv_bfloat16* __restrict__ Thi,
    __nv_bfloat16* __restrict__ Tlo, int K, int N)
{
    __shared__ float ts[32][33];
    int k0 = blockIdx.y * 32, n0 = blockIdx.x * 32;
    int tx = threadIdx.x & 31, ty = threadIdx.x >> 5;
#pragma unroll
    for (int r = ty; r < 32; r += 8)
        ts[r][tx] = W[(size_t)(k0 + r) * N + n0 + tx];
    __syncthreads();
#pragma unroll
    for (int r = ty; r < 32; r += 8) {
        float x = ts[tx][r];
        __nv_bfloat16 h = __float2bfloat16(x);
        __nv_bfloat16 l = __float2bfloat16(x - __bfloat162float(h));
        size_t o = (size_t)(n0 + r) * K + k0 + tx;
        Thi[o] = h;
        Tlo[o] = l;
    }
}

// ---------------- warp-MMA split-bf16 GEMM, 3-stage pipeline, fused epilogues ----
// MODE 0: C = A@B^T + bias (fp32 out)
// MODE 1: QKV — split-store repacked Q(+rwb/rrb)/K/V
// MODE 2: rk — split-store repacked R
#define GBK 32
#define GT_BYTES (128 * GBK * 2)
#define GSTAGE   (4 * GT_BYTES)
#define GSMEM    (3 * GSTAGE)     // 3 stages = 98304

__device__ __forceinline__ uint32_t gswz(int row, int ch) {
    return (uint32_t)(row * 64 + ((ch ^ ((row >> 1) & 3)) << 4));
}

template <int MODE>
__global__ __launch_bounds__(256) void gemm_fused_kernel(
    const __nv_bfloat16* __restrict__ Ahi, const __nv_bfloat16* __restrict__ Alo,
    const __nv_bfloat16* __restrict__ Bhi, const __nv_bfloat16* __restrict__ Blo,
    const float* __restrict__ bias, float* __restrict__ C,
    const float* __restrict__ rwb, const float* __restrict__ rrb,
    int M, int N, int K)
{
    extern __shared__ char smem[];
    const uint32_t sb = smem_u32(smem);
    const int tid = threadIdx.x;
    const int wid = tid >> 5, lane = tid & 31;
    const int wm = wid >> 1, wn = wid & 1;
    const int m0 = blockIdx.y * 128;
    const int n0 = blockIdx.x * 128;
    const int kiters = K / GBK;

    const int r0 = tid >> 2, c0 = tid & 3;
    const int r1 = (tid + 256) >> 2, c1 = tid & 3;

    auto load_stage = [&](int stg, int k0) {
        const uint32_t st = sb + stg * GSTAGE;
        const uint32_t o0 = gswz(r0, c0), o1 = gswz(r1, c1);
        const size_t ga0 = (size_t)(m0 + r0) * K + k0 + c0 * 8;
        const size_t ga1 = (size_t)(m0 + r1) * K + k0 + c1 * 8;
        const size_t gb0 = (size_t)(n0 + r0) * K + k0 + c0 * 8;
        const size_t gb1 = (size_t)(n0 + r1) * K + k0 + c1 * 8;
        cp16(st + o0,                Ahi + ga0);
        cp16(st + o1,                Ahi + ga1);
        cp16(st + GT_BYTES + o0,     Alo + ga0);
        cp16(st + GT_BYTES + o1,     Alo + ga1);
        cp16(st + 2 * GT_BYTES + o0, Bhi + gb0);
        cp16(st + 2 * GT_BYTES + o1, Bhi + gb1);
        cp16(st + 3 * GT_BYTES + o0, Blo + gb0);
        cp16(st + 3 * GT_BYTES + o1, Blo + gb1);
        cp_commit();
    };

    float acc[2][8][4];
#pragma unroll
    for (int i = 0; i < 2; i++)
#pragma unroll
        for (int j = 0; j < 8; j++)
#pragma unroll
            for (int t = 0; t < 4; t++) acc[i][j][t] = 0.f;

    const int lrow = lane & 15, lkh = lane >> 4;

    // prologue: stages 0 and 1 in flight
    load_stage(0, 0);
    load_stage(1, GBK);

    int stg = 0;
    for (int c = 0; c < kiters; ++c) {
        if (c + 1 < kiters) cp_wait1(); else cp_wait0();   // stage c resident
        __syncthreads();   // all warps done reading the stage we refill below
        if (c + 2 < kiters) {
            int nxt = stg + 2; if (nxt >= 3) nxt -= 3;     // (stg+2) % 3
            load_stage(nxt, (c + 2) * GBK);
        }
        const uint32_t st = sb + stg * GSTAGE;
#pragma unroll
        for (int s = 0; s < 2; ++s) {
            const int ch = s * 2 + lkh;
            uint32_t ah[2][4], al[2][4];
#pragma unroll
            for (int i = 0; i < 2; i++) {
                const int row = wm * 32 + i * 16 + lrow;
                const uint32_t o = gswz(row, ch);
                ldsm4(ah[i][0], ah[i][1], ah[i][2], ah[i][3], st + o);
                ldsm4(al[i][0], al[i][1], al[i][2], al[i][3], st + GT_BYTES + o);
            }
            uint32_t bh[8][2], bl[8][2];
#pragma unroll
            for (int g = 0; g < 4; g++) {
                const int row = wn * 64 + g * 16 + lrow;
                const uint32_t o = gswz(row, ch);
                uint32_t t0, t1, t2, t3;
                ldsm4(t0, t1, t2, t3, st + 2 * GT_BYTES + o);
                bh[2 * g][0] = t0; bh[2 * g][1] = t2;
                bh[2 * g + 1][0] = t1; bh[2 * g + 1][1] = t3;
                ldsm4(t0, t1, t2, t3, st + 3 * GT_BYTES + o);
                bl[2 * g][0] = t0; bl[2 * g][1] = t2;
                bl[2 * g + 1][0] = t1; bl[2 * g + 1][1] = t3;
            }
#pragma unroll
            for (int i = 0; i < 2; i++)
#pragma unroll
                for (int j = 0; j < 8; j++) {
                    mma16816(acc[i][j], ah[i], bh[j]);
                    mma16816(acc[i][j], ah[i], bl[j]);
                    mma16816(acc[i][j], al[i], bh[j]);
                }
        }
        stg = (stg == 2) ? 0 : stg + 1;
    }

    // ---- epilogues ----
    const int sec = n0 >> 10;  // MODE 1: 0=q,1=k,2=v
#pragma unroll
    for (int i = 0; i < 2; i++) {
        const int row0 = m0 + wm * 32 + i * 16 + (lane >> 2);
#pragma unroll
        for (int j = 0; j < 8; j++) {
            const int col = n0 + wn * 64 + j * 8 + (lane & 3) * 2;
            const float2 bz = *(const float2*)(bias + col);
            if (MODE == 0) {
                float2 v0, v1;
                v0.x = acc[i][j][0] + bz.x; v0.y = acc[i][j][1] + bz.y;
                v1.x = acc[i][j][2] + bz.x; v1.y = acc[i][j][3] + bz.y;
                *(float2*)(C + (size_t)row0 * N + col)       = v0;
                *(float2*)(C + (size_t)(row0 + 8) * N + col) = v1;
            } else if (MODE == 1) {
                const int nh = (col & 1023) >> 6;
                const int d  = col & 63;
#pragma unroll
                for (int rr = 0; rr < 2; rr++) {
                    const int row = row0 + rr * 8;
                    const float v0 = acc[i][j][rr * 2 + 0] + bz.x;
                    const float v1 = acc[i][j][rr * 2 + 1] + bz.y;
                    const int qi = row >> 2, bb = row & 3;
                    const size_t o = (((size_t)(bb * NH + nh) * QL + qi) << 6) + d;
                    if (sec == 0) {
                        const float2 bw = *(const float2*)(rwb + (col & 1023));
                        const float2 br = *(const float2*)(rrb + (col & 1023));
                        split2(g_QWh + o, g_QWl + o, v0 + bw.x, v1 + bw.y);
                        split2(g_QRh + o, g_QRl + o, v0 + br.x, v1 + br.y);
                    } else if (sec == 1) {
                        split2(g_Kph + o, g_Kpl + o, v0, v1);
                    } else {
                        split2(g_Vph + o, g_Vpl + o, v0, v1);
                    }
                }
            } else {  // MODE 2: rk
                const int nh = col >> 6, d = col & 63;
#pragma unroll
                for (int rr = 0; rr < 2; rr++) {
                    const int row = row0 + rr * 8;
                    const float v0 = acc[i][j][rr * 2 + 0] + bz.x;
                    const float v1 = acc[i][j][rr * 2 + 1] + bz.y;
                    const size_t o = (((size_t)nh * QL + row) << 6) + d;
                    split2(g_Rph + o, g_Rpl + o, v0, v1);
                }
            }
        }
    }
}

// ---------------- MMA flash rel-attention (epilogue -> split vec) ----------------
#define ATTM_SMEM 98304

__global__ __launch_bounds__(128) void attn_mma_kernel()
{
    extern __shared__ char sm[];
    const uint32_t sb = smem_u32(sm);
    const int it = blockIdx.x, n = blockIdx.y, b = blockIdx.z;
    const int i0 = it * 64;
    const int tid = threadIdx.x, w = tid >> 5, lane = tid & 31;
    const int q4 = lane & 3, g8 = lane >> 2;
    const int lrow = lane & 15, lhalf = lane >> 4;
    const size_t bn = (size_t)(b * NH + n) * QL;
    const size_t rn = (size_t)n * QL;

    const uint32_t uQ = sb;
    const uint32_t uKh = sb + 32768, uKl = uKh + 8192;
    const uint32_t uVh = uKl + 8192, uVl = uVh + 8192;
    const uint32_t uRh = sb + 65536, uRl = uRh + 16384;
    float* bdp = (float*)sm;  // sBD overlay on Q region: [64][128] fp32

#pragma unroll
    for (int k = 0; k < 4; k++) {
        int c = tid + k * 128;
        int row = c >> 3, ch = c & 7;
        size_t g = (bn + i0 + row) * 64 + ch * 8;
        uint32_t so = ASWZ(row, ch);
        cp16(uQ + so,         g_QWh + g);
        cp16(uQ + 8192 + so,  g_QWl + g);
        cp16(uQ + 16384 + so, g_QRh + g);
        cp16(uQ + 24576 + so, g_QRl + g);
    }
    cp_commit(); cp_wait0();
    __syncthreads();

    uint32_t qwh[4][4], qwl[4][4], qrh[4][4], qrl[4][4];
#pragma unroll
    for (int ks = 0; ks < 4; ks++) {
        uint32_t so = ASWZ(w * 16 + lrow, ks * 2 + lhalf);
        ldsm4(qwh[ks][0], qwh[ks][1], qwh[ks][2], qwh[ks][3], uQ + so);
        ldsm4(qwl[ks][0], qwl[ks][1], qwl[ks][2], qwl[ks][3], uQ + 8192 + so);
        ldsm4(qrh[ks][0], qrh[ks][1], qrh[ks][2], qrh[ks][3], uQ + 16384 + so);
        ldsm4(qrl[ks][0], qrl[ks][1], qrl[ks][2], qrl[ks][3], uQ + 24576 + so);
    }
    __syncthreads();  // Q smem now free -> sBD

    float oacc[8][4];
#pragma unroll
    for (int f = 0; f < 8; f++)
#pragma unroll
        for (int e = 0; e < 4; e++) oacc[f][e] = 0.f;
    float m0 = -1e30f, m1 = -1e30f, l0 = 0.f, l1 = 0.f;
    const int rb = 48 - w * 16;
    const int il0 = w * 16 + g8, il1 = il0 + 8;

    for (int jt = 0; jt <= it; jt++) {
        const int j0 = jt * 64;
#pragma unroll
        for (int k = 0; k < 4; k++) {
            int c = tid + k * 128;
            int row = c >> 3, ch = c & 7;
            size_t g = (bn + j0 + row) * 64 + ch * 8;
            uint32_t so = ASWZ(row, ch);
            cp16(uKh + so, g_Kph + g);
            cp16(uKl + so, g_Kpl + g);
            cp16(uVh + so, g_Vph + g);
            cp16(uVl + so, g_Vpl + g);
        }
        const int mb = j0 - i0 + 960;
#pragma unroll
        for (int k = 0; k < 8; k++) {
            int c = tid + k * 128;
            int row = c >> 3, ch = c & 7;
            int m = mb + row; if (m > 1023) m = 1023;
            size_t g = (rn + m) * 64 + ch * 8;
            uint32_t so = ASWZ(row, ch);
            cp16(uRh + so, g_Rph + g);
            cp16(uRl + so, g_Rpl + g);
        }
        cp_commit(); cp_wait0();
        __syncthreads();

        // BD banded GEMM
        float bd[10][4];
#pragma unroll
        for (int f = 0; f < 10; f++)
#pragma unroll
            for (int e = 0; e < 4; e++) bd[f][e] = 0.f;
#pragma unroll
        for (int ks = 0; ks < 4; ks++) {
            uint32_t bh_[10][2], bl_[10][2];
#pragma unroll
            for (int g = 0; g < 5; g++) {
                uint32_t so = ASWZ(rb + g * 16 + lrow, ks * 2 + lhalf);
                uint32_t t0, t1, t2, t3;
                ldsm4(t0, t1, t2, t3, uRh + so);
                bh_[2 * g][0] = t0; bh_[2 * g][1] = t2;
                bh_[2 * g + 1][0] = t1; bh_[2 * g + 1][1] = t3;
                ldsm4(t0, t1, t2, t3, uRl + so);
                bl_[2 * g][0] = t0; bl_[2 * g][1] = t2;
                bl_[2 * g + 1][0] = t1; bl_[2 * g + 1][1] = t3;
            }
#pragma unroll
            for (int f = 0; f < 10; f++) {
                mma16816(bd[f], qrh[ks], bh_[f]);
                mma16816(bd[f], qrh[ks], bl_[f]);
                mma16816(bd[f], qrl[ks], bh_[f]);
            }
        }
        __syncwarp();
#pragma unroll
        for (int f = 0; f < 10; f++) {
            int col = rb + f * 8 + q4 * 2;
            *(float2*)(sm + ((w * 16 + g8) * 128 + col) * 4)     = make_float2(bd[f][0], bd[f][1]);
            *(float2*)(sm + ((w * 16 + g8 + 8) * 128 + col) * 4) = make_float2(bd[f][2], bd[f][3]);
        }
        __syncwarp();

        // AC GEMM
        float acc[8][4];
#pragma unroll
        for (int f = 0; f < 8; f++)
#pragma unroll
            for (int e = 0; e < 4; e++) acc[f][e] = 0.f;
#pragma unroll
        for (int ks = 0; ks < 4; ks++) {
            uint32_t kh_[8][2], kl_[8][2];
#pragma unroll
            for (int g = 0; g < 4; g++) {
                uint32_t so = ASWZ(g * 16 + lrow, ks * 2 + lhalf);
                uint32_t t0, t1, t2, t3;
                ldsm4(t0, t1, t2, t3, uKh + so);
                kh_[2 * g][0] = t0; kh_[2 * g][1] = t2;
                kh_[2 * g + 1][0] = t1; kh_[2 * g + 1][1] = t3;
                ldsm4(t0, t1, t2, t3, uKl + so);
                kl_[2 * g][0] = t0; kl_[2 * g][1] = t2;
                kl_[2 * g + 1][0] = t1; kl_[2 * g + 1][1] = t3;
            }
#pragma unroll
            for (int f = 0; f < 8; f++) {
                mma16816(acc[f], qwh[ks], kh_[f]);
                mma16816(acc[f], qwh[ks], kl_[f]);
                mma16816(acc[f], qwl[ks], kh_[f]);
            }
        }

        // softmax on fragments
        const bool diag = (jt == it);
        float mx0 = -1e30f, mx1 = -1e30f;
#pragma unroll
        for (int f = 0; f < 8; f++) {
#pragma unroll
            for (int e = 0; e < 4; e++) {
                int jl = f * 8 + q4 * 2 + (e & 1);
                int il = (e < 2) ? il0 : il1;
                float sv = (acc[f][e] + bdp[il * 128 + (jl - il + 63)]) * ATT_SCALE;
                if (diag && jl > il) sv = -1e30f;
                acc[f][e] = sv;
            }
            mx0 = fmaxf(mx0, fmaxf(acc[f][0], acc[f][1]));
            mx1 = fmaxf(mx1, fmaxf(acc[f][2], acc[f][3]));
        }
        mx0 = fmaxf(mx0, __shfl_xor_sync(0xffffffffu, mx0, 1));
        mx0 = fmaxf(mx0, __shfl_xor_sync(0xffffffffu, mx0, 2));
        mx1 = fmaxf(mx1, __shfl_xor_sync(0xffffffffu, mx1, 1));
        mx1 = fmaxf(mx1, __shfl_xor_sync(0xffffffffu, mx1, 2));
        float mn0 = fmaxf(m0, mx0), mn1 = fmaxf(m1, mx1);
        float al0 = __expf(m0 - mn0), al1 = __expf(m1 - mn1);
        m0 = mn0; m1 = mn1;

        float rs0 = 0.f, rs1 = 0.f;
        uint32_t pah[4][4], pal[4][4];
#pragma unroll
        for (int f = 0; f < 8; f++) {
            float p0 = __expf(acc[f][0] - mn0), p1 = __expf(acc[f][1] - mn0);
            float p2 = __expf(acc[f][2] - mn1), p3 = __expf(acc[f][3] - mn1);
            rs0 += p0 + p1; rs1 += p2 + p3;
            __nv_bfloat16 h0 = __float2bfloat16(p0), h1 = __float2bfloat16(p1);
            __nv_bfloat16 h2 = __float2bfloat16(p2), h3 = __float2bfloat16(p3);
            uint32_t uh01, uh23, ul01, ul23;
            *(__nv_bfloat162*)&uh01 = __halves2bfloat162(h0, h1);
            *(__nv_bfloat162*)&uh23 = __halves2bfloat162(h2, h3);
            ul01 = packbf(p0 - __bfloat162float(h0), p1 - __bfloat162float(h1));
            ul23 = packbf(p2 - __bfloat162float(h2), p3 - __bfloat162float(h3));
            int kb = f >> 1;
            if ((f & 1) == 0) { pah[kb][0] = uh01; pah[kb][1] = uh23;
                                pal[kb][0] = ul01; pal[kb][1] = ul23; }
            else              { pah[kb][2] = uh01; pah[kb][3] = uh23;
                                pal[kb][2] = ul01; pal[kb][3] = ul23; }
        }
        rs0 += __shfl_xor_sync(0xffffffffu, rs0, 1);
        rs0 += __shfl_xor_sync(0xffffffffu, rs0, 2);
        rs1 += __shfl_xor_sync(0xffffffffu, rs1, 1);
        rs1 += __shfl_xor_sync(0xffffffffu, rs1, 2);
        l0 = l0 * al0 + rs0;
        l1 = l1 * al1 + rs1;
#pragma unroll
        for (int f = 0; f < 8; f++) {
            oacc[f][0] *= al0; oacc[f][1] *= al0;
            oacc[f][2] *= al1; oacc[f][3] *= al1;
        }

        // PV
#pragma unroll
        for (int kb = 0; kb < 4; kb++) {
            uint32_t vh_[8][2], vl_[8][2];
#pragma unroll
            for (int g = 0; g < 4; g++) {
                uint32_t so = ASWZ(kb * 16 + lrow, g * 2 + lhalf);
                uint32_t t0, t1, t2, t3;
                ldsm4t(t0, t1, t2, t3, uVh + so);
                vh_[2 * g][0] = t0; vh_[2 * g][1] = t1;
                vh_[2 * g + 1][0] = t2; vh_[2 * g + 1][1] = t3;
                ldsm4t(t0, t1, t2, t3, uVl + so);
                vl_[2 * g][0] = t0; vl_[2 * g][1] = t1;
                vl_[2 * g + 1][0] = t2; vl_[2 * g + 1][1] = t3;
            }
#pragma unroll
            for (int f = 0; f < 8; f++) {
                mma16816(oacc[f], pah[kb], vh_[f]);
                mma16816(oacc[f], pal[kb], vh_[f]);
                mma16816(oacc[f], pah[kb], vl_[f]);
            }
        }
        __syncthreads();
    }

    // epilogue: split-store directly into vec_hi/vec_lo
    float inv0 = 1.f / l0, inv1 = 1.f / l1;
    int gi0 = i0 + il0, gi1 = i0 + il1;
#pragma unroll
    for (int f = 0; f < 8; f++) {
        int d = f * 8 + q4 * 2;
        size_t o0 = ((size_t)gi0 * BSZ + b) * HD + n * 64 + d;
        size_t o1 = ((size_t)gi1 * BSZ + b) * HD + n * 64 + d;
        split2(g_vec_hi + o0, g_vec_lo + o0, oacc[f][0] * inv0, oacc[f][1] * inv0);
        split2(g_vec_hi + o1, g_vec_lo + o1, oacc[f][2] * inv1, oacc[f][3] * inv1);
    }
}

// ---------------- residual + LayerNorm ----------------
__global__ __launch_bounds__(256) void ln_kernel(
    const float* __restrict__ w, const float* __restrict__ ao,
    const float* __restrict__ g, const float* __restrict__ bb,
    float* __restrict__ out)
{
    __shared__ float red[8];
    __shared__ float s_mu, s_rstd;
    const int row = blockIdx.x;
    const int tid = threadIdx.x;
    const int lane = tid & 31, wid = tid >> 5;
    const size_t base = (size_t)row * DM + tid * 4;

    float4 wv = *(const float4*)(w + base);
    float4 av = *(const float4*)(ao + base);
    float x0 = wv.x + av.x, x1 = wv.y + av.y, x2 = wv.z + av.z, x3 = wv.w + av.w;

    float s = x0 + x1 + x2 + x3;
#pragma unroll
    for (int o = 16; o >= 1; o >>= 1) s += __shfl_xor_sync(0xffffffffu, s, o);
    if (lane == 0) red[wid] = s;
    __syncthreads();
    if (tid == 0) {
        float t = 0.f;
#pragma unroll
        for (int i = 0; i < 8; i++) t += red[i];
        s_mu = t * (1.0f / DM);
    }
    __syncthreads();
    const float mu = s_mu;

    float d0 = x0 - mu, d1 = x1 - mu, d2 = x2 - mu, d3 = x3 - mu;
    float ss = d0 * d0 + d1 * d1 + d2 * d2 + d3 * d3;
#pragma unroll
    for (int o = 16; o >= 1; o >>= 1) ss += __shfl_xor_sync(0xffffffffu, ss, o);
    if (lane == 0) red[wid] = ss;
    __syncthreads();
    if (tid == 0) {
        float t = 0.f;
#pragma unroll
        for (int i = 0; i < 8; i++) t += red[i];
        s_rstd = rsqrtf(t * (1.0f / DM) + 1e-5f);
    }
    __syncthreads();
    const float rstd = s_rstd;

    float4 gv = *(const float4*)(g + tid * 4);
    float4 bv = *(const float4*)(bb + tid * 4);
    float4 o4;
    o4.x = d0 * rstd * gv.x + bv.x;
    o4.y = d1 * rstd * gv.y + bv.y;
    o4.z = d2 * rstd * gv.z + bv.z;
    o4.w = d3 * rstd * gv.w + bv.w;
    *(float4*)(out + base) = o4;
}

// ---------------- launch ----------------
extern "C" void kernel_launch(void* const* d_in, const int* in_sizes, int n_in,
                              void* d_out, int out_size)
{
    (void)in_sizes; (void)n_in; (void)out_size;
    const float* w     = (const float*)d_in[0];
    const float* r     = (const float*)d_in[1];
    const float* rwb   = (const float*)d_in[2];
    const float* rrb   = (const float*)d_in[3];
    const float* qkv_w = (const float*)d_in[4];
    const float* qkv_b = (const float*)d_in[5];
    const float* rk_w  = (const float*)d_in[6];
    const float* rk_b  = (const float*)d_in[7];
    const float* o_w   = (const float*)d_in[8];
    const float* o_b   = (const float*)d_in[9];
    const float* ln_g  = (const float*)d_in[10];
    const float* ln_b  = (const float*)d_in[11];
    float* out = (float*)d_out;

    float* ao;
    cudaGetSymbolAddress((void**)&ao, g_ao);
    __nv_bfloat16 *w_hi, *w_lo, *r_hi, *r_lo, *vec_hi, *vec_lo;
    __nv_bfloat16 *qkvwT_hi, *qkvwT_lo, *rkwT_hi, *rkwT_lo, *owT_hi, *owT_lo;
    cudaGetSymbolAddress((void**)&w_hi, g_w_hi);
    cudaGetSymbolAddress((void**)&w_lo, g_w_lo);
    cudaGetSymbolAddress((void**)&r_hi, g_r_hi);
    cudaGetSymbolAddress((void**)&r_lo, g_r_lo);
    cudaGetSymbolAddress((void**)&vec_hi, g_vec_hi);
    cudaGetSymbolAddress((void**)&vec_lo, g_vec_lo);
    cudaGetSymbolAddress((void**)&qkvwT_hi, g_qkvwT_hi);
    cudaGetSymbolAddress((void**)&qkvwT_lo, g_qkvwT_lo);
    cudaGetSymbolAddress((void**)&rkwT_hi, g_rkwT_hi);
    cudaGetSymbolAddress((void**)&rkwT_lo, g_rkwT_lo);
    cudaGetSymbolAddress((void**)&owT_hi, g_owT_hi);
    cudaGetSymbolAddress((void**)&owT_lo, g_owT_lo);

    cudaFuncSetAttribute(gemm_fused_kernel<0>, cudaFuncAttributeMaxDynamicSharedMemorySize, GSMEM);
    cudaFuncSetAttribute(gemm_fused_kernel<1>, cudaFuncAttributeMaxDynamicSharedMemorySize, GSMEM);
    cudaFuncSetAttribute(gemm_fused_kernel<2>, cudaFuncAttributeMaxDynamicSharedMemorySize, GSMEM);
    cudaFuncSetAttribute(attn_mma_kernel, cudaFuncAttributeMaxDynamicSharedMemorySize, ATTM_SMEM);

    // idx 0-2: conversions needed for QKV GEMM
    split_kernel<<<(NROWS * DM / 4 + 255) / 256, 256>>>(
        (const float4*)w, (__nv_bfloat162*)w_hi, (__nv_bfloat162*)w_lo, NROWS * DM / 4);
    split_kernel<<<(QL * DM / 4 + 255) / 256, 256>>>(
        (const float4*)r, (__nv_bfloat162*)r_hi, (__nv_bfloat162*)r_lo, QL * DM / 4);
    transpose_split_kernel<<<dim3(QKV3 / 32, DM / 32), 256>>>(qkv_w, qkvwT_hi, qkvwT_lo, DM, QKV3);

    // idx 3 (ncu capture slot): QKV GEMM with fused repack epilogue
    gemm_fused_kernel<1><<<dim3(QKV3 / 128, NROWS / 128), 256, GSMEM>>>(
        w_hi, w_lo, qkvwT_hi, qkvwT_lo, qkv_b, nullptr, rwb, rrb, NROWS, QKV3, DM);

    // rk GEMM with fused repack epilogue
    transpose_split_kernel<<<dim3(HD / 32, DM / 32), 256>>>(rk_w, rkwT_hi, rkwT_lo, DM, HD);
    gemm_fused_kernel<2><<<dim3(HD / 128, QL / 128), 256, GSMEM>>>(
        r_hi, r_lo, rkwT_hi, rkwT_lo, rk_b, nullptr, nullptr, nullptr, QL, HD, DM);

    // fused MMA rel-attention (writes split vec directly)
    attn_mma_kernel<<<dim3(QL / 64, NH, BSZ), 128, ATTM_SMEM>>>();

    // out-proj
    transpose_split_kernel<<<dim3(DM / 32, HD / 32), 256>>>(o_w, owT_hi, owT_lo, HD, DM);
    gemm_fused_kernel<0><<<dim3(DM / 128, NROWS / 128), 256, GSMEM>>>(
        vec_hi, vec_lo, owT_hi, owT_lo, o_b, ao, nullptr, nullptr, NROWS, DM, DM);

    // residual + LayerNorm
    ln_kernel<<<NROWS, 256>>>(w, ao, ln_g, ln_b, out);
}

// round 13
// speedup vs baseline: 1.0939x; 1.0939x over previous
#include <cuda_runtime.h>
#include <cuda_bf16.h>
#include <cstdint>

#define QL   1024
#define BSZ  4
#define DM   1024
#define NH   16
#define DH   64
#define HD   1024      // NH*DH
#define QKV3 3072
#define NROWS (QL*BSZ) // 4096
#define ATT_SCALE 0.125f

// ---------------- scratch (no allocation allowed) ----------------
__device__ __align__(16) float g_ao[(size_t)NROWS * DM];

// split-bf16 GEMM operands
__device__ __align__(16) __nv_bfloat16 g_w_hi[(size_t)NROWS * DM];
__device__ __align__(16) __nv_bfloat16 g_w_lo[(size_t)NROWS * DM];
__device__ __align__(16) __nv_bfloat16 g_r_hi[(size_t)QL * DM];
__device__ __align__(16) __nv_bfloat16 g_r_lo[(size_t)QL * DM];
__device__ __align__(16) __nv_bfloat16 g_vec_hi[(size_t)NROWS * HD];
__device__ __align__(16) __nv_bfloat16 g_vec_lo[(size_t)NROWS * HD];
__device__ __align__(16) __nv_bfloat16 g_qkvwT_hi[(size_t)QKV3 * DM];
__device__ __align__(16) __nv_bfloat16 g_qkvwT_lo[(size_t)QKV3 * DM];
__device__ __align__(16) __nv_bfloat16 g_rkwT_hi[(size_t)HD * DM];
__device__ __align__(16) __nv_bfloat16 g_rkwT_lo[(size_t)HD * DM];
__device__ __align__(16) __nv_bfloat16 g_owT_hi[(size_t)DM * HD];
__device__ __align__(16) __nv_bfloat16 g_owT_lo[(size_t)DM * HD];

// attention repacked operands: [b][n][row][64] bf16 (written by GEMM epilogues)
__device__ __align__(16) __nv_bfloat16 g_QWh[(size_t)NROWS * HD];
__device__ __align__(16) __nv_bfloat16 g_QWl[(size_t)NROWS * HD];
__device__ __align__(16) __nv_bfloat16 g_QRh[(size_t)NROWS * HD];
__device__ __align__(16) __nv_bfloat16 g_QRl[(size_t)NROWS * HD];
__device__ __align__(16) __nv_bfloat16 g_Kph[(size_t)NROWS * HD];
__device__ __align__(16) __nv_bfloat16 g_Kpl[(size_t)NROWS * HD];
__device__ __align__(16) __nv_bfloat16 g_Vph[(size_t)NROWS * HD];
__device__ __align__(16) __nv_bfloat16 g_Vpl[(size_t)NROWS * HD];
__device__ __align__(16) __nv_bfloat16 g_Rph[(size_t)NH * QL * DH];
__device__ __align__(16) __nv_bfloat16 g_Rpl[(size_t)NH * QL * DH];

// ---------------- PTX helpers ----------------
__device__ __forceinline__ uint32_t smem_u32(const void* p) {
    uint32_t a;
    asm("{ .reg .u64 t; cvta.to.shared.u64 t, %1; cvt.u32.u64 %0, t; }" : "=r"(a) : "l"(p));
    return a;
}
__device__ __forceinline__ void cp16(uint32_t s, const void* g) {
    asm volatile("cp.async.cg.shared.global [%0], [%1], 16;" :: "r"(s), "l"(g));
}
__device__ __forceinline__ void cp_commit() {
    asm volatile("cp.async.commit_group;" ::: "memory");
}
__device__ __forceinline__ void cp_wait0() {
    asm volatile("cp.async.wait_group 0;" ::: "memory");
}
__device__ __forceinline__ void cp_wait1() {
    asm volatile("cp.async.wait_group 1;" ::: "memory");
}
__device__ __forceinline__ void ldsm4(uint32_t& r0, uint32_t& r1, uint32_t& r2, uint32_t& r3,
                                      uint32_t a) {
    asm volatile("ldmatrix.sync.aligned.m8n8.x4.shared.b16 {%0,%1,%2,%3}, [%4];"
                 : "=r"(r0), "=r"(r1), "=r"(r2), "=r"(r3) : "r"(a));
}
__device__ __forceinline__ void ldsm4t(uint32_t& r0, uint32_t& r1, uint32_t& r2, uint32_t& r3,
                                       uint32_t a) {
    asm volatile("ldmatrix.sync.aligned.m8n8.x4.trans.shared.b16 {%0,%1,%2,%3}, [%4];"
                 : "=r"(r0), "=r"(r1), "=r"(r2), "=r"(r3) : "r"(a));
}
__device__ __forceinline__ void mma16816(float* d, const uint32_t* a, const uint32_t* b) {
    asm volatile("mma.sync.aligned.m16n8k16.row.col.f32.bf16.bf16.f32 "
                 "{%0,%1,%2,%3}, {%4,%5,%6,%7}, {%8,%9}, {%0,%1,%2,%3};"
                 : "+f"(d[0]), "+f"(d[1]), "+f"(d[2]), "+f"(d[3])
                 : "r"(a[0]), "r"(a[1]), "r"(a[2]), "r"(a[3]), "r"(b[0]), "r"(b[1]));
}
__device__ __forceinline__ uint32_t packbf(float a, float b) {
    __nv_bfloat162 t = __halves2bfloat162(__float2bfloat16(a), __float2bfloat16(b));
    uint32_t u;
    *(__nv_bfloat162*)&u = t;
    return u;
}
__device__ __forceinline__ void split2(__nv_bfloat16* hi, __nv_bfloat16* lo, float a, float b) {
    __nv_bfloat16 h0 = __float2bfloat16(a), h1 = __float2bfloat16(b);
    *(__nv_bfloat162*)hi = __halves2bfloat162(h0, h1);
    *(__nv_bfloat162*)lo = __halves2bfloat162(
        __float2bfloat16(a - __bfloat162float(h0)),
        __float2bfloat16(b - __bfloat162float(h1)));
}

// swizzled byte offset for [rows][64 bf16] tiles (128B rows)
#define ASWZ(row, ch) ((uint32_t)((row) * 128 + ((((ch) ^ ((row) & 7))) << 4)))

// ---------------- split / transpose-split conversion kernels ----------------
__global__ __launch_bounds__(256) void split_kernel(
    const float4* __restrict__ x, __nv_bfloat162* __restrict__ hi,
    __nv_bfloat162* __restrict__ lo, int n4)
{
    int i = blockIdx.x * 256 + threadIdx.x;
    if (i >= n4) return;
    float4 v = x[i];
    __nv_bfloat16 h0 = __float2bfloat16(v.x);
    __nv_bfloat16 h1 = __float2bfloat16(v.y);
    __nv_bfloat16 h2 = __float2bfloat16(v.z);
    __nv_bfloat16 h3 = __float2bfloat16(v.w);
    __nv_bfloat16 l0 = __float2bfloat16(v.x - __bfloat162float(h0));
    __nv_bfloat16 l1 = __float2bfloat16(v.y - __bfloat162float(h1));
    __nv_bfloat16 l2 = __float2bfloat16(v.z - __bfloat162float(h2));
    __nv_bfloat16 l3 = __float2bfloat16(v.w - __bfloat162float(h3));
    hi[2 * i]     = __halves2bfloat162(h0, h1);
    hi[2 * i + 1] = __halves2bfloat162(h2, h3);
    lo[2 * i]     = __halves2bfloat162(l0, l1);
    lo[2 * i + 1] = __halves2bfloat162(l2, l3);
}

__global__ __launch_bounds__(256) void transpose_split_kernel(
    const float* __restrict__ W, __nv_bfloat16* __restrict__ Thi,
    __nv_bfloat16* __restrict__ Tlo, int K, int N)
{
    __shared__ float ts[32][33];
    int k0 = blockIdx.y * 32, n0 = blockIdx.x * 32;
    int tx = threadIdx.x & 31, ty = threadIdx.x >> 5;
#pragma unroll
    for (int r = ty; r < 32; r += 8)
        ts[r][tx] = W[(size_t)(k0 + r) * N + n0 + tx];
    __syncthreads();
#pragma unroll
    for (int r = ty; r < 32; r += 8) {
        float x = ts[tx][r];
        __nv_bfloat16 h = __float2bfloat16(x);
        __nv_bfloat16 l = __float2bfloat16(x - __bfloat162float(h));
        size_t o = (size_t)(n0 + r) * K + k0 + tx;
        Thi[o] = h;
        Tlo[o] = l;
    }
}

// ---------------- warp-MMA split-bf16 GEMM, 3-stage pipeline, fused epilogues ----
// MODE 0: C = A@B^T + bias (fp32 out)
// MODE 1: QKV — split-store repacked Q(+rwb/rrb)/K/V
// MODE 2: rk — split-store repacked R
#define GBK 32
#define GT_BYTES (128 * GBK * 2)
#define GSTAGE   (4 * GT_BYTES)
#define GSMEM    (3 * GSTAGE)     // 3 stages = 98304

__device__ __forceinline__ uint32_t gswz(int row, int ch) {
    return (uint32_t)(row * 64 + ((ch ^ ((row >> 1) & 3)) << 4));
}

template <int MODE>
__global__ __launch_bounds__(256, 2) void gemm_fused_kernel(
    const __nv_bfloat16* __restrict__ Ahi, const __nv_bfloat16* __restrict__ Alo,
    const __nv_bfloat16* __restrict__ Bhi, const __nv_bfloat16* __restrict__ Blo,
    const float* __restrict__ bias, float* __restrict__ C,
    const float* __restrict__ rwb, const float* __restrict__ rrb,
    int M, int N, int K)
{
    extern __shared__ char smem[];
    const uint32_t sb = smem_u32(smem);
    const int tid = threadIdx.x;
    const int wid = tid >> 5, lane = tid & 31;
    const int wm = wid >> 1, wn = wid & 1;
    const int m0 = blockIdx.y * 128;
    const int n0 = blockIdx.x * 128;
    const int kiters = K / GBK;

    const int r0 = tid >> 2, c0 = tid & 3;
    const int r1 = (tid + 256) >> 2, c1 = tid & 3;

    auto load_stage = [&](int stg, int k0) {
        const uint32_t st = sb + stg * GSTAGE;
        const uint32_t o0 = gswz(r0, c0), o1 = gswz(r1, c1);
        const size_t ga0 = (size_t)(m0 + r0) * K + k0 + c0 * 8;
        const size_t ga1 = (size_t)(m0 + r1) * K + k0 + c1 * 8;
        const size_t gb0 = (size_t)(n0 + r0) * K + k0 + c0 * 8;
        const size_t gb1 = (size_t)(n0 + r1) * K + k0 + c1 * 8;
        cp16(st + o0,                Ahi + ga0);
        cp16(st + o1,                Ahi + ga1);
        cp16(st + GT_BYTES + o0,     Alo + ga0);
        cp16(st + GT_BYTES + o1,     Alo + ga1);
        cp16(st + 2 * GT_BYTES + o0, Bhi + gb0);
        cp16(st + 2 * GT_BYTES + o1, Bhi + gb1);
        cp16(st + 3 * GT_BYTES + o0, Blo + gb0);
        cp16(st + 3 * GT_BYTES + o1, Blo + gb1);
        cp_commit();
    };

    float acc[2][8][4];
#pragma unroll
    for (int i = 0; i < 2; i++)
#pragma unroll
        for (int j = 0; j < 8; j++)
#pragma unroll
            for (int t = 0; t < 4; t++) acc[i][j][t] = 0.f;

    const int lrow = lane & 15, lkh = lane >> 4;

    // prologue: stages 0 and 1 in flight
    load_stage(0, 0);
    load_stage(1, GBK);

    int stg = 0;
    for (int c = 0; c < kiters; ++c) {
        if (c + 1 < kiters) cp_wait1(); else cp_wait0();   // stage c resident
        __syncthreads();   // all warps done reading the stage we refill below
        if (c + 2 < kiters) {
            int nxt = stg + 2; if (nxt >= 3) nxt -= 3;     // (stg+2) % 3
            load_stage(nxt, (c + 2) * GBK);
        }
        const uint32_t st = sb + stg * GSTAGE;
#pragma unroll
        for (int s = 0; s < 2; ++s) {
            const int ch = s * 2 + lkh;
            uint32_t ah[2][4], al[2][4];
#pragma unroll
            for (int i = 0; i < 2; i++) {
                const int row = wm * 32 + i * 16 + lrow;
                const uint32_t o = gswz(row, ch);
                ldsm4(ah[i][0], ah[i][1], ah[i][2], ah[i][3], st + o);
                ldsm4(al[i][0], al[i][1], al[i][2], al[i][3], st + GT_BYTES + o);
            }
            uint32_t bh[8][2], bl[8][2];
#pragma unroll
            for (int g = 0; g < 4; g++) {
                const int row = wn * 64 + g * 16 + lrow;
                const uint32_t o = gswz(row, ch);
                uint32_t t0, t1, t2, t3;
                ldsm4(t0, t1, t2, t3, st + 2 * GT_BYTES + o);
                bh[2 * g][0] = t0; bh[2 * g][1] = t2;
                bh[2 * g + 1][0] = t1; bh[2 * g + 1][1] = t3;
                ldsm4(t0, t1, t2, t3, st + 3 * GT_BYTES + o);
                bl[2 * g][0] = t0; bl[2 * g][1] = t2;
                bl[2 * g + 1][0] = t1; bl[2 * g + 1][1] = t3;
            }
#pragma unroll
            for (int i = 0; i < 2; i++)
#pragma unroll
                for (int j = 0; j < 8; j++) {
                    mma16816(acc[i][j], ah[i], bh[j]);
                    mma16816(acc[i][j], ah[i], bl[j]);
                    mma16816(acc[i][j], al[i], bh[j]);
                }
        }
        stg = (stg == 2) ? 0 : stg + 1;
    }

    // ---- epilogues ----
    const int sec = n0 >> 10;  // MODE 1: 0=q,1=k,2=v
#pragma unroll
    for (int i = 0; i < 2; i++) {
        const int row0 = m0 + wm * 32 + i * 16 + (lane >> 2);
#pragma unroll
        for (int j = 0; j < 8; j++) {
            const int col = n0 + wn * 64 + j * 8 + (lane & 3) * 2;
            const float2 bz = *(const float2*)(bias + col);
            if (MODE == 0) {
                float2 v0, v1;
                v0.x = acc[i][j][0] + bz.x; v0.y = acc[i][j][1] + bz.y;
                v1.x = acc[i][j][2] + bz.x; v1.y = acc[i][j][3] + bz.y;
                *(float2*)(C + (size_t)row0 * N + col)       = v0;
                *(float2*)(C + (size_t)(row0 + 8) * N + col) = v1;
            } else if (MODE == 1) {
                const int nh = (col & 1023) >> 6;
                const int d  = col & 63;
#pragma unroll
                for (int rr = 0; rr < 2; rr++) {
                    const int row = row0 + rr * 8;
                    const float v0 = acc[i][j][rr * 2 + 0] + bz.x;
                    const float v1 = acc[i][j][rr * 2 + 1] + bz.y;
                    const int qi = row >> 2, bb = row & 3;
                    const size_t o = (((size_t)(bb * NH + nh) * QL + qi) << 6) + d;
                    if (sec == 0) {
                        const float2 bw = *(const float2*)(rwb + (col & 1023));
                        const float2 br = *(const float2*)(rrb + (col & 1023));
                        split2(g_QWh + o, g_QWl + o, v0 + bw.x, v1 + bw.y);
                        split2(g_QRh + o, g_QRl + o, v0 + br.x, v1 + br.y);
                    } else if (sec == 1) {
                        split2(g_Kph + o, g_Kpl + o, v0, v1);
                    } else {
                        split2(g_Vph + o, g_Vpl + o, v0, v1);
                    }
                }
            } else {  // MODE 2: rk
                const int nh = col >> 6, d = col & 63;
#pragma unroll
                for (int rr = 0; rr < 2; rr++) {
                    const int row = row0 + rr * 8;
                    const float v0 = acc[i][j][rr * 2 + 0] + bz.x;
                    const float v1 = acc[i][j][rr * 2 + 1] + bz.y;
                    const size_t o = (((size_t)nh * QL + row) << 6) + d;
                    split2(g_Rph + o, g_Rpl + o, v0, v1);
                }
            }
        }
    }
}

// ---------------- MMA flash rel-attention (epilogue -> split vec) ----------------
#define ATTM_SMEM 98304

__global__ __launch_bounds__(128) void attn_mma_kernel()
{
    extern __shared__ char sm[];
    const uint32_t sb = smem_u32(sm);
    const int it = blockIdx.x, n = blockIdx.y, b = blockIdx.z;
    const int i0 = it * 64;
    const int tid = threadIdx.x, w = tid >> 5, lane = tid & 31;
    const int q4 = lane & 3, g8 = lane >> 2;
    const int lrow = lane & 15, lhalf = lane >> 4;
    const size_t bn = (size_t)(b * NH + n) * QL;
    const size_t rn = (size_t)n * QL;

    const uint32_t uQ = sb;
    const uint32_t uKh = sb + 32768, uKl = uKh + 8192;
    const uint32_t uVh = uKl + 8192, uVl = uVh + 8192;
    const uint32_t uRh = sb + 65536, uRl = uRh + 16384;
    float* bdp = (float*)sm;  // sBD overlay on Q region: [64][128] fp32

#pragma unroll
    for (int k = 0; k < 4; k++) {
        int c = tid + k * 128;
        int row = c >> 3, ch = c & 7;
        size_t g = (bn + i0 + row) * 64 + ch * 8;
        uint32_t so = ASWZ(row, ch);
        cp16(uQ + so,         g_QWh + g);
        cp16(uQ + 8192 + so,  g_QWl + g);
        cp16(uQ + 16384 + so, g_QRh + g);
        cp16(uQ + 24576 + so, g_QRl + g);
    }
    cp_commit(); cp_wait0();
    __syncthreads();

    uint32_t qwh[4][4], qwl[4][4], qrh[4][4], qrl[4][4];
#pragma unroll
    for (int ks = 0; ks < 4; ks++) {
        uint32_t so = ASWZ(w * 16 + lrow, ks * 2 + lhalf);
        ldsm4(qwh[ks][0], qwh[ks][1], qwh[ks][2], qwh[ks][3], uQ + so);
        ldsm4(qwl[ks][0], qwl[ks][1], qwl[ks][2], qwl[ks][3], uQ + 8192 + so);
        ldsm4(qrh[ks][0], qrh[ks][1], qrh[ks][2], qrh[ks][3], uQ + 16384 + so);
        ldsm4(qrl[ks][0], qrl[ks][1], qrl[ks][2], qrl[ks][3], uQ + 24576 + so);
    }
    __syncthreads();  // Q smem now free -> sBD

    float oacc[8][4];
#pragma unroll
    for (int f = 0; f < 8; f++)
#pragma unroll
        for (int e = 0; e < 4; e++) oacc[f][e] = 0.f;
    float m0 = -1e30f, m1 = -1e30f, l0 = 0.f, l1 = 0.f;
    const int rb = 48 - w * 16;
    const int il0 = w * 16 + g8, il1 = il0 + 8;

    for (int jt = 0; jt <= it; jt++) {
        const int j0 = jt * 64;
#pragma unroll
        for (int k = 0; k < 4; k++) {
            int c = tid + k * 128;
            int row = c >> 3, ch = c & 7;
            size_t g = (bn + j0 + row) * 64 + ch * 8;
            uint32_t so = ASWZ(row, ch);
            cp16(uKh + so, g_Kph + g);
            cp16(uKl + so, g_Kpl + g);
            cp16(uVh + so, g_Vph + g);
            cp16(uVl + so, g_Vpl + g);
        }
        const int mb = j0 - i0 + 960;
#pragma unroll
        for (int k = 0; k < 8; k++) {
            int c = tid + k * 128;
            int row = c >> 3, ch = c & 7;
            int m = mb + row; if (m > 1023) m = 1023;
            size_t g = (rn + m) * 64 + ch * 8;
            uint32_t so = ASWZ(row, ch);
            cp16(uRh + so, g_Rph + g);
            cp16(uRl + so, g_Rpl + g);
        }
        cp_commit(); cp_wait0();
        __syncthreads();

        // BD banded GEMM
        float bd[10][4];
#pragma unroll
        for (int f = 0; f < 10; f++)
#pragma unroll
            for (int e = 0; e < 4; e++) bd[f][e] = 0.f;
#pragma unroll
        for (int ks = 0; ks < 4; ks++) {
            uint32_t bh_[10][2], bl_[10][2];
#pragma unroll
            for (int g = 0; g < 5; g++) {
                uint32_t so = ASWZ(rb + g * 16 + lrow, ks * 2 + lhalf);
                uint32_t t0, t1, t2, t3;
                ldsm4(t0, t1, t2, t3, uRh + so);
                bh_[2 * g][0] = t0; bh_[2 * g][1] = t2;
                bh_[2 * g + 1][0] = t1; bh_[2 * g + 1][1] = t3;
                ldsm4(t0, t1, t2, t3, uRl + so);
                bl_[2 * g][0] = t0; bl_[2 * g][1] = t2;
                bl_[2 * g + 1][0] = t1; bl_[2 * g + 1][1] = t3;
            }
#pragma unroll
            for (int f = 0; f < 10; f++) {
                mma16816(bd[f], qrh[ks], bh_[f]);
                mma16816(bd[f], qrh[ks], bl_[f]);
                mma16816(bd[f], qrl[ks], bh_[f]);
            }
        }
        __syncwarp();
#pragma unroll
        for (int f = 0; f < 10; f++) {
            int col = rb + f * 8 + q4 * 2;
            *(float2*)(sm + ((w * 16 + g8) * 128 + col) * 4)     = make_float2(bd[f][0], bd[f][1]);
            *(float2*)(sm + ((w * 16 + g8 + 8) * 128 + col) * 4) = make_float2(bd[f][2], bd[f][3]);
        }
        __syncwarp();

        // AC GEMM
        float acc[8][4];
#pragma unroll
        for (int f = 0; f < 8; f++)
#pragma unroll
            for (int e = 0; e < 4; e++) acc[f][e] = 0.f;
#pragma unroll
        for (int ks = 0; ks < 4; ks++) {
            uint32_t kh_[8][2], kl_[8][2];
#pragma unroll
            for (int g = 0; g < 4; g++) {
                uint32_t so = ASWZ(g * 16 + lrow, ks * 2 + lhalf);
                uint32_t t0, t1, t2, t3;
                ldsm4(t0, t1, t2, t3, uKh + so);
                kh_[2 * g][0] = t0; kh_[2 * g][1] = t2;
                kh_[2 * g + 1][0] = t1; kh_[2 * g + 1][1] = t3;
                ldsm4(t0, t1, t2, t3, uKl + so);
                kl_[2 * g][0] = t0; kl_[2 * g][1] = t2;
                kl_[2 * g + 1][0] = t1; kl_[2 * g + 1][1] = t3;
            }
#pragma unroll
            for (int f = 0; f < 8; f++) {
                mma16816(acc[f], qwh[ks], kh_[f]);
                mma16816(acc[f], qwh[ks], kl_[f]);
                mma16816(acc[f], qwl[ks], kh_[f]);
            }
        }

        // softmax on fragments
        const bool diag = (jt == it);
        float mx0 = -1e30f, mx1 = -1e30f;
#pragma unroll
        for (int f = 0; f < 8; f++) {
#pragma unroll
            for (int e = 0; e < 4; e++) {
                int jl = f * 8 + q4 * 2 + (e & 1);
                int il = (e < 2) ? il0 : il1;
                float sv = (acc[f][e] + bdp[il * 128 + (jl - il + 63)]) * ATT_SCALE;
                if (diag && jl > il) sv = -1e30f;
                acc[f][e] = sv;
            }
            mx0 = fmaxf(mx0, fmaxf(acc[f][0], acc[f][1]));
            mx1 = fmaxf(mx1, fmaxf(acc[f][2], acc[f][3]));
        }
        mx0 = fmaxf(mx0, __shfl_xor_sync(0xffffffffu, mx0, 1));
        mx0 = fmaxf(mx0, __shfl_xor_sync(0xffffffffu, mx0, 2));
        mx1 = fmaxf(mx1, __shfl_xor_sync(0xffffffffu, mx1, 1));
        mx1 = fmaxf(mx1, __shfl_xor_sync(0xffffffffu, mx1, 2));
        float mn0 = fmaxf(m0, mx0), mn1 = fmaxf(m1, mx1);
        float al0 = __expf(m0 - mn0), al1 = __expf(m1 - mn1);
        m0 = mn0; m1 = mn1;

        float rs0 = 0.f, rs1 = 0.f;
        uint32_t pah[4][4], pal[4][4];
#pragma unroll
        for (int f = 0; f < 8; f++) {
            float p0 = __expf(acc[f][0] - mn0), p1 = __expf(acc[f][1] - mn0);
            float p2 = __expf(acc[f][2] - mn1), p3 = __expf(acc[f][3] - mn1);
            rs0 += p0 + p1; rs1 += p2 + p3;
            __nv_bfloat16 h0 = __float2bfloat16(p0), h1 = __float2bfloat16(p1);
            __nv_bfloat16 h2 = __float2bfloat16(p2), h3 = __float2bfloat16(p3);
            uint32_t uh01, uh23, ul01, ul23;
            *(__nv_bfloat162*)&uh01 = __halves2bfloat162(h0, h1);
            *(__nv_bfloat162*)&uh23 = __halves2bfloat162(h2, h3);
            ul01 = packbf(p0 - __bfloat162float(h0), p1 - __bfloat162float(h1));
            ul23 = packbf(p2 - __bfloat162float(h2), p3 - __bfloat162float(h3));
            int kb = f >> 1;
            if ((f & 1) == 0) { pah[kb][0] = uh01; pah[kb][1] = uh23;
                                pal[kb][0] = ul01; pal[kb][1] = ul23; }
            else              { pah[kb][2] = uh01; pah[kb][3] = uh23;
                                pal[kb][2] = ul01; pal[kb][3] = ul23; }
        }
        rs0 += __shfl_xor_sync(0xffffffffu, rs0, 1);
        rs0 += __shfl_xor_sync(0xffffffffu, rs0, 2);
        rs1 += __shfl_xor_sync(0xffffffffu, rs1, 1);
        rs1 += __shfl_xor_sync(0xffffffffu, rs1, 2);
        l0 = l0 * al0 + rs0;
        l1 = l1 * al1 + rs1;
#pragma unroll
        for (int f = 0; f < 8; f++) {
            oacc[f][0] *= al0; oacc[f][1] *= al0;
            oacc[f][2] *= al1; oacc[f][3] *= al1;
        }

        // PV
#pragma unroll
        for (int kb = 0; kb < 4; kb++) {
            uint32_t vh_[8][2], vl_[8][2];
#pragma unroll
            for (int g = 0; g < 4; g++) {
                uint32_t so = ASWZ(kb * 16 + lrow, g * 2 + lhalf);
                uint32_t t0, t1, t2, t3;
                ldsm4t(t0, t1, t2, t3, uVh + so);
                vh_[2 * g][0] = t0; vh_[2 * g][1] = t1;
                vh_[2 * g + 1][0] = t2; vh_[2 * g + 1][1] = t3;
                ldsm4t(t0, t1, t2, t3, uVl + so);
                vl_[2 * g][0] = t0; vl_[2 * g][1] = t1;
                vl_[2 * g + 1][0] = t2; vl_[2 * g + 1][1] = t3;
            }
#pragma unroll
            for (int f = 0; f < 8; f++) {
                mma16816(oacc[f], pah[kb], vh_[f]);
                mma16816(oacc[f], pal[kb], vh_[f]);
                mma16816(oacc[f], pah[kb], vl_[f]);
            }
        }
        __syncthreads();
    }

    // epilogue: split-store directly into vec_hi/vec_lo
    float inv0 = 1.f / l0, inv1 = 1.f / l1;
    int gi0 = i0 + il0, gi1 = i0 + il1;
#pragma unroll
    for (int f = 0; f < 8; f++) {
        int d = f * 8 + q4 * 2;
        size_t o0 = ((size_t)gi0 * BSZ + b) * HD + n * 64 + d;
        size_t o1 = ((size_t)gi1 * BSZ + b) * HD + n * 64 + d;
        split2(g_vec_hi + o0, g_vec_lo + o0, oacc[f][0] * inv0, oacc[f][1] * inv0);
        split2(g_vec_hi + o1, g_vec_lo + o1, oacc[f][2] * inv1, oacc[f][3] * inv1);
    }
}

// ---------------- residual + LayerNorm ----------------
__global__ __launch_bounds__(256) void ln_kernel(
    const float* __restrict__ w, const float* __restrict__ ao,
    const float* __restrict__ g, const float* __restrict__ bb,
    float* __restrict__ out)
{
    __shared__ float red[8];
    __shared__ float s_mu, s_rstd;
    const int row = blockIdx.x;
    const int tid = threadIdx.x;
    const int lane = tid & 31, wid = tid >> 5;
    const size_t base = (size_t)row * DM + tid * 4;

    float4 wv = *(const float4*)(w + base);
    float4 av = *(const float4*)(ao + base);
    float x0 = wv.x + av.x, x1 = wv.y + av.y, x2 = wv.z + av.z, x3 = wv.w + av.w;

    float s = x0 + x1 + x2 + x3;
#pragma unroll
    for (int o = 16; o >= 1; o >>= 1) s += __shfl_xor_sync(0xffffffffu, s, o);
    if (lane == 0) red[wid] = s;
    __syncthreads();
    if (tid == 0) {
        float t = 0.f;
#pragma unroll
        for (int i = 0; i < 8; i++) t += red[i];
        s_mu = t * (1.0f / DM);
    }
    __syncthreads();
    const float mu = s_mu;

    float d0 = x0 - mu, d1 = x1 - mu, d2 = x2 - mu, d3 = x3 - mu;
    float ss = d0 * d0 + d1 * d1 + d2 * d2 + d3 * d3;
#pragma unroll
    for (int o = 16; o >= 1; o >>= 1) ss += __shfl_xor_sync(0xffffffffu, ss, o);
    if (lane == 0) red[wid] = ss;
    __syncthreads();
    if (tid == 0) {
        float t = 0.f;
#pragma unroll
        for (int i = 0; i < 8; i++) t += red[i];
        s_rstd = rsqrtf(t * (1.0f / DM) + 1e-5f);
    }
    __syncthreads();
    const float rstd = s_rstd;

    float4 gv = *(const float4*)(g + tid * 4);
    float4 bv = *(const float4*)(bb + tid * 4);
    float4 o4;
    o4.x = d0 * rstd * gv.x + bv.x;
    o4.y = d1 * rstd * gv.y + bv.y;
    o4.z = d2 * rstd * gv.z + bv.z;
    o4.w = d3 * rstd * gv.w + bv.w;
    *(float4*)(out + base) = o4;
}

// ---------------- launch ----------------
extern "C" void kernel_launch(void* const* d_in, const int* in_sizes, int n_in,
                              void* d_out, int out_size)
{
    (void)in_sizes; (void)n_in; (void)out_size;
    const float* w     = (const float*)d_in[0];
    const float* r     = (const float*)d_in[1];
    const float* rwb   = (const float*)d_in[2];
    const float* rrb   = (const float*)d_in[3];
    const float* qkv_w = (const float*)d_in[4];
    const float* qkv_b = (const float*)d_in[5];
    const float* rk_w  = (const float*)d_in[6];
    const float* rk_b  = (const float*)d_in[7];
    const float* o_w   = (const float*)d_in[8];
    const float* o_b   = (const float*)d_in[9];
    const float* ln_g  = (const float*)d_in[10];
    const float* ln_b  = (const float*)d_in[11];
    float* out = (float*)d_out;

    float* ao;
    cudaGetSymbolAddress((void**)&ao, g_ao);
    __nv_bfloat16 *w_hi, *w_lo, *r_hi, *r_lo, *vec_hi, *vec_lo;
    __nv_bfloat16 *qkvwT_hi, *qkvwT_lo, *rkwT_hi, *rkwT_lo, *owT_hi, *owT_lo;
    cudaGetSymbolAddress((void**)&w_hi, g_w_hi);
    cudaGetSymbolAddress((void**)&w_lo, g_w_lo);
    cudaGetSymbolAddress((void**)&r_hi, g_r_hi);
    cudaGetSymbolAddress((void**)&r_lo, g_r_lo);
    cudaGetSymbolAddress((void**)&vec_hi, g_vec_hi);
    cudaGetSymbolAddress((void**)&vec_lo, g_vec_lo);
    cudaGetSymbolAddress((void**)&qkvwT_hi, g_qkvwT_hi);
    cudaGetSymbolAddress((void**)&qkvwT_lo, g_qkvwT_lo);
    cudaGetSymbolAddress((void**)&rkwT_hi, g_rkwT_hi);
    cudaGetSymbolAddress((void**)&rkwT_lo, g_rkwT_lo);
    cudaGetSymbolAddress((void**)&owT_hi, g_owT_hi);
    cudaGetSymbolAddress((void**)&owT_lo, g_owT_lo);

    cudaFuncSetAttribute(gemm_fused_kernel<0>, cudaFuncAttributeMaxDynamicSharedMemorySize, GSMEM);
    cudaFuncSetAttribute(gemm_fused_kernel<1>, cudaFuncAttributeMaxDynamicSharedMemorySize, GSMEM);
    cudaFuncSetAttribute(gemm_fused_kernel<2>, cudaFuncAttributeMaxDynamicSharedMemorySize, GSMEM);
    cudaFuncSetAttribute(attn_mma_kernel, cudaFuncAttributeMaxDynamicSharedMemorySize, ATTM_SMEM);

    // idx 0-2: conversions needed for QKV GEMM
    split_kernel<<<(NROWS * DM / 4 + 255) / 256, 256>>>(
        (const float4*)w, (__nv_bfloat162*)w_hi, (__nv_bfloat162*)w_lo, NROWS * DM / 4);
    split_kernel<<<(QL * DM / 4 + 255) / 256, 256>>>(
        (const float4*)r, (__nv_bfloat162*)r_hi, (__nv_bfloat162*)r_lo, QL * DM / 4);
    transpose_split_kernel<<<dim3(QKV3 / 32, DM / 32), 256>>>(qkv_w, qkvwT_hi, qkvwT_lo, DM, QKV3);

    // idx 3 (ncu capture slot): QKV GEMM with fused repack epilogue
    gemm_fused_kernel<1><<<dim3(QKV3 / 128, NROWS / 128), 256, GSMEM>>>(
        w_hi, w_lo, qkvwT_hi, qkvwT_lo, qkv_b, nullptr, rwb, rrb, NROWS, QKV3, DM);

    // rk GEMM with fused repack epilogue
    transpose_split_kernel<<<dim3(HD / 32, DM / 32), 256>>>(rk_w, rkwT_hi, rkwT_lo, DM, HD);
    gemm_fused_kernel<2><<<dim3(HD / 128, QL / 128), 256, GSMEM>>>(
        r_hi, r_lo, rkwT_hi, rkwT_lo, rk_b, nullptr, nullptr, nullptr, QL, HD, DM);

    // fused MMA rel-attention (writes split vec directly)
    attn_mma_kernel<<<dim3(QL / 64, NH, BSZ), 128, ATTM_SMEM>>>();

    // out-proj
    transpose_split_kernel<<<dim3(DM / 32, HD / 32), 256>>>(o_w, owT_hi, owT_lo, HD, DM);
    gemm_fused_kernel<0><<<dim3(DM / 128, NROWS / 128), 256, GSMEM>>>(
        vec_hi, vec_lo, owT_hi, owT_lo, o_b, ao, nullptr, nullptr, NROWS, DM, DM);

    // residual + LayerNorm
    ln_kernel<<<NROWS, 256>>>(w, ao, ln_g, ln_b, out);
}

// round 14
// speedup vs baseline: 1.0999x; 1.0054x over previous
#include <cuda_runtime.h>
#include <cuda_bf16.h>
#include <cstdint>

#define QL   1024
#define BSZ  4
#define DM   1024
#define NH   16
#define DH   64
#define HD   1024      // NH*DH
#define QKV3 3072
#define NROWS (QL*BSZ) // 4096
#define ATT_SCALE 0.125f

// ---------------- scratch (no allocation allowed) ----------------
__device__ __align__(16) float g_ao[(size_t)NROWS * DM];

// split-bf16 GEMM operands
__device__ __align__(16) __nv_bfloat16 g_w_hi[(size_t)NROWS * DM];
__device__ __align__(16) __nv_bfloat16 g_w_lo[(size_t)NROWS * DM];
__device__ __align__(16) __nv_bfloat16 g_r_hi[(size_t)QL * DM];
__device__ __align__(16) __nv_bfloat16 g_r_lo[(size_t)QL * DM];
__device__ __align__(16) __nv_bfloat16 g_vec_hi[(size_t)NROWS * HD];
__device__ __align__(16) __nv_bfloat16 g_vec_lo[(size_t)NROWS * HD];
__device__ __align__(16) __nv_bfloat16 g_qkvwT_hi[(size_t)QKV3 * DM];
__device__ __align__(16) __nv_bfloat16 g_qkvwT_lo[(size_t)QKV3 * DM];
__device__ __align__(16) __nv_bfloat16 g_rkwT_hi[(size_t)HD * DM];
__device__ __align__(16) __nv_bfloat16 g_rkwT_lo[(size_t)HD * DM];
__device__ __align__(16) __nv_bfloat16 g_owT_hi[(size_t)DM * HD];
__device__ __align__(16) __nv_bfloat16 g_owT_lo[(size_t)DM * HD];

// attention repacked operands: [b][n][row][64] bf16 (written by GEMM epilogues)
__device__ __align__(16) __nv_bfloat16 g_QWh[(size_t)NROWS * HD];
__device__ __align__(16) __nv_bfloat16 g_QWl[(size_t)NROWS * HD];
__device__ __align__(16) __nv_bfloat16 g_QRh[(size_t)NROWS * HD];
__device__ __align__(16) __nv_bfloat16 g_QRl[(size_t)NROWS * HD];
__device__ __align__(16) __nv_bfloat16 g_Kph[(size_t)NROWS * HD];
__device__ __align__(16) __nv_bfloat16 g_Kpl[(size_t)NROWS * HD];
__device__ __align__(16) __nv_bfloat16 g_Vph[(size_t)NROWS * HD];
__device__ __align__(16) __nv_bfloat16 g_Vpl[(size_t)NROWS * HD];
__device__ __align__(16) __nv_bfloat16 g_Rph[(size_t)NH * QL * DH];
__device__ __align__(16) __nv_bfloat16 g_Rpl[(size_t)NH * QL * DH];

// ---------------- PTX helpers ----------------
__device__ __forceinline__ uint32_t smem_u32(const void* p) {
    uint32_t a;
    asm("{ .reg .u64 t; cvta.to.shared.u64 t, %1; cvt.u32.u64 %0, t; }" : "=r"(a) : "l"(p));
    return a;
}
__device__ __forceinline__ void cp16(uint32_t s, const void* g) {
    asm volatile("cp.async.cg.shared.global [%0], [%1], 16;" :: "r"(s), "l"(g));
}
__device__ __forceinline__ void cp_commit() {
    asm volatile("cp.async.commit_group;" ::: "memory");
}
__device__ __forceinline__ void cp_wait0() {
    asm volatile("cp.async.wait_group 0;" ::: "memory");
}
__device__ __forceinline__ void cp_wait1() {
    asm volatile("cp.async.wait_group 1;" ::: "memory");
}
__device__ __forceinline__ void cp_wait2() {
    asm volatile("cp.async.wait_group 2;" ::: "memory");
}
__device__ __forceinline__ void ldsm4(uint32_t& r0, uint32_t& r1, uint32_t& r2, uint32_t& r3,
                                      uint32_t a) {
    asm volatile("ldmatrix.sync.aligned.m8n8.x4.shared.b16 {%0,%1,%2,%3}, [%4];"
                 : "=r"(r0), "=r"(r1), "=r"(r2), "=r"(r3) : "r"(a));
}
__device__ __forceinline__ void ldsm4t(uint32_t& r0, uint32_t& r1, uint32_t& r2, uint32_t& r3,
                                       uint32_t a) {
    asm volatile("ldmatrix.sync.aligned.m8n8.x4.trans.shared.b16 {%0,%1,%2,%3}, [%4];"
                 : "=r"(r0), "=r"(r1), "=r"(r2), "=r"(r3) : "r"(a));
}
__device__ __forceinline__ void mma16816(float* d, const uint32_t* a, const uint32_t* b) {
    asm volatile("mma.sync.aligned.m16n8k16.row.col.f32.bf16.bf16.f32 "
                 "{%0,%1,%2,%3}, {%4,%5,%6,%7}, {%8,%9}, {%0,%1,%2,%3};"
                 : "+f"(d[0]), "+f"(d[1]), "+f"(d[2]), "+f"(d[3])
                 : "r"(a[0]), "r"(a[1]), "r"(a[2]), "r"(a[3]), "r"(b[0]), "r"(b[1]));
}
__device__ __forceinline__ uint32_t packbf(float a, float b) {
    __nv_bfloat162 t = __halves2bfloat162(__float2bfloat16(a), __float2bfloat16(b));
    uint32_t u;
    *(__nv_bfloat162*)&u = t;
    return u;
}
__device__ __forceinline__ void split2(__nv_bfloat16* hi, __nv_bfloat16* lo, float a, float b) {
    __nv_bfloat16 h0 = __float2bfloat16(a), h1 = __float2bfloat16(b);
    *(__nv_bfloat162*)hi = __halves2bfloat162(h0, h1);
    *(__nv_bfloat162*)lo = __halves2bfloat162(
        __float2bfloat16(a - __bfloat162float(h0)),
        __float2bfloat16(b - __bfloat162float(h1)));
}

// swizzled byte offset for [rows][64 bf16] tiles (128B rows)
#define ASWZ(row, ch) ((uint32_t)((row) * 128 + ((((ch) ^ ((row) & 7))) << 4)))

// ---------------- split / transpose-split conversion kernels ----------------
__global__ __launch_bounds__(256) void split_kernel(
    const float4* __restrict__ x, __nv_bfloat162* __restrict__ hi,
    __nv_bfloat162* __restrict__ lo, int n4)
{
    int i = blockIdx.x * 256 + threadIdx.x;
    if (i >= n4) return;
    float4 v = x[i];
    __nv_bfloat16 h0 = __float2bfloat16(v.x);
    __nv_bfloat16 h1 = __float2bfloat16(v.y);
    __nv_bfloat16 h2 = __float2bfloat16(v.z);
    __nv_bfloat16 h3 = __float2bfloat16(v.w);
    __nv_bfloat16 l0 = __float2bfloat16(v.x - __bfloat162float(h0));
    __nv_bfloat16 l1 = __float2bfloat16(v.y - __bfloat162float(h1));
    __nv_bfloat16 l2 = __float2bfloat16(v.z - __bfloat162float(h2));
    __nv_bfloat16 l3 = __float2bfloat16(v.w - __bfloat162float(h3));
    hi[2 * i]     = __halves2bfloat162(h0, h1);
    hi[2 * i + 1] = __halves2bfloat162(h2, h3);
    lo[2 * i]     = __halves2bfloat162(l0, l1);
    lo[2 * i + 1] = __halves2bfloat162(l2, l3);
}

__global__ __launch_bounds__(256) void transpose_split_kernel(
    const float* __restrict__ W, __nv_bfloat16* __restrict__ Thi,
    __nv_bfloat16* __restrict__ Tlo, int K, int N)
{
    __shared__ float ts[32][33];
    int k0 = blockIdx.y * 32, n0 = blockIdx.x * 32;
    int tx = threadIdx.x & 31, ty = threadIdx.x >> 5;
#pragma unroll
    for (int r = ty; r < 32; r += 8)
        ts[r][tx] = W[(size_t)(k0 + r) * N + n0 + tx];
    __syncthreads();
#pragma unroll
    for (int r = ty; r < 32; r += 8) {
        float x = ts[tx][r];
        __nv_bfloat16 h = __float2bfloat16(x);
        __nv_bfloat16 l = __float2bfloat16(x - __bfloat162float(h));
        size_t o = (size_t)(n0 + r) * K + k0 + tx;
        Thi[o] = h;
        Tlo[o] = l;
    }
}

// ---------------- warp-MMA split-bf16 GEMM, 3-stage pipeline, fused epilogues ----
// MODE 0: C = A@B^T + bias (fp32 out)
// MODE 1: QKV — split-store repacked Q(+rwb/rrb)/K/V
// MODE 2: rk — split-store repacked R
#define GBK 32
#define GT_BYTES (128 * GBK * 2)
#define GSTAGE   (4 * GT_BYTES)
#define GSMEM    (3 * GSTAGE)     // 3 stages = 98304

__device__ __forceinline__ uint32_t gswz(int row, int ch) {
    return (uint32_t)(row * 64 + ((ch ^ ((row >> 1) & 3)) << 4));
}

template <int MODE>
__global__ __launch_bounds__(256, 2) void gemm_fused_kernel(
    const __nv_bfloat16* __restrict__ Ahi, const __nv_bfloat16* __restrict__ Alo,
    const __nv_bfloat16* __restrict__ Bhi, const __nv_bfloat16* __restrict__ Blo,
    const float* __restrict__ bias, float* __restrict__ C,
    const float* __restrict__ rwb, const float* __restrict__ rrb,
    int M, int N, int K)
{
    extern __shared__ char smem[];
    const uint32_t sb = smem_u32(smem);
    const int tid = threadIdx.x;
    const int wid = tid >> 5, lane = tid & 31;
    const int wm = wid >> 1, wn = wid & 1;
    const int m0 = blockIdx.y * 128;
    const int n0 = blockIdx.x * 128;
    const int kiters = K / GBK;

    const int r0 = tid >> 2, c0 = tid & 3;
    const int r1 = (tid + 256) >> 2, c1 = tid & 3;

    auto load_stage = [&](int stg, int k0) {
        const uint32_t st = sb + stg * GSTAGE;
        const uint32_t o0 = gswz(r0, c0), o1 = gswz(r1, c1);
        const size_t ga0 = (size_t)(m0 + r0) * K + k0 + c0 * 8;
        const size_t ga1 = (size_t)(m0 + r1) * K + k0 + c1 * 8;
        const size_t gb0 = (size_t)(n0 + r0) * K + k0 + c0 * 8;
        const size_t gb1 = (size_t)(n0 + r1) * K + k0 + c1 * 8;
        cp16(st + o0,                Ahi + ga0);
        cp16(st + o1,                Ahi + ga1);
        cp16(st + GT_BYTES + o0,     Alo + ga0);
        cp16(st + GT_BYTES + o1,     Alo + ga1);
        cp16(st + 2 * GT_BYTES + o0, Bhi + gb0);
        cp16(st + 2 * GT_BYTES + o1, Bhi + gb1);
        cp16(st + 3 * GT_BYTES + o0, Blo + gb0);
        cp16(st + 3 * GT_BYTES + o1, Blo + gb1);
        cp_commit();
    };

    float acc[2][8][4];
#pragma unroll
    for (int i = 0; i < 2; i++)
#pragma unroll
        for (int j = 0; j < 8; j++)
#pragma unroll
            for (int t = 0; t < 4; t++) acc[i][j][t] = 0.f;

    const int lrow = lane & 15, lkh = lane >> 4;

    // prologue: stages 0 and 1 in flight
    load_stage(0, 0);
    load_stage(1, GBK);

    int stg = 0;
    for (int c = 0; c < kiters; ++c) {
        if (c + 1 < kiters) cp_wait1(); else cp_wait0();   // stage c resident
        __syncthreads();   // all warps done reading the stage we refill below
        if (c + 2 < kiters) {
            int nxt = stg + 2; if (nxt >= 3) nxt -= 3;     // (stg+2) % 3
            load_stage(nxt, (c + 2) * GBK);
        }
        const uint32_t st = sb + stg * GSTAGE;
#pragma unroll
        for (int s = 0; s < 2; ++s) {
            const int ch = s * 2 + lkh;
            uint32_t ah[2][4], al[2][4];
#pragma unroll
            for (int i = 0; i < 2; i++) {
                const int row = wm * 32 + i * 16 + lrow;
                const uint32_t o = gswz(row, ch);
                ldsm4(ah[i][0], ah[i][1], ah[i][2], ah[i][3], st + o);
                ldsm4(al[i][0], al[i][1], al[i][2], al[i][3], st + GT_BYTES + o);
            }
            uint32_t bh[8][2], bl[8][2];
#pragma unroll
            for (int g = 0; g < 4; g++) {
                const int row = wn * 64 + g * 16 + lrow;
                const uint32_t o = gswz(row, ch);
                uint32_t t0, t1, t2, t3;
                ldsm4(t0, t1, t2, t3, st + 2 * GT_BYTES + o);
                bh[2 * g][0] = t0; bh[2 * g][1] = t2;
                bh[2 * g + 1][0] = t1; bh[2 * g + 1][1] = t3;
                ldsm4(t0, t1, t2, t3, st + 3 * GT_BYTES + o);
                bl[2 * g][0] = t0; bl[2 * g][1] = t2;
                bl[2 * g + 1][0] = t1; bl[2 * g + 1][1] = t3;
            }
#pragma unroll
            for (int i = 0; i < 2; i++)
#pragma unroll
                for (int j = 0; j < 8; j++) {
                    mma16816(acc[i][j], ah[i], bh[j]);
                    mma16816(acc[i][j], ah[i], bl[j]);
                    mma16816(acc[i][j], al[i], bh[j]);
                }
        }
        stg = (stg == 2) ? 0 : stg + 1;
    }

    // ---- epilogues ----
    const int sec = n0 >> 10;  // MODE 1: 0=q,1=k,2=v
#pragma unroll
    for (int i = 0; i < 2; i++) {
        const int row0 = m0 + wm * 32 + i * 16 + (lane >> 2);
#pragma unroll
        for (int j = 0; j < 8; j++) {
            const int col = n0 + wn * 64 + j * 8 + (lane & 3) * 2;
            const float2 bz = *(const float2*)(bias + col);
            if (MODE == 0) {
                float2 v0, v1;
                v0.x = acc[i][j][0] + bz.x; v0.y = acc[i][j][1] + bz.y;
                v1.x = acc[i][j][2] + bz.x; v1.y = acc[i][j][3] + bz.y;
                *(float2*)(C + (size_t)row0 * N + col)       = v0;
                *(float2*)(C + (size_t)(row0 + 8) * N + col) = v1;
            } else if (MODE == 1) {
                const int nh = (col & 1023) >> 6;
                const int d  = col & 63;
#pragma unroll
                for (int rr = 0; rr < 2; rr++) {
                    const int row = row0 + rr * 8;
                    const float v0 = acc[i][j][rr * 2 + 0] + bz.x;
                    const float v1 = acc[i][j][rr * 2 + 1] + bz.y;
                    const int qi = row >> 2, bb = row & 3;
                    const size_t o = (((size_t)(bb * NH + nh) * QL + qi) << 6) + d;
                    if (sec == 0) {
                        const float2 bw = *(const float2*)(rwb + (col & 1023));
                        const float2 br = *(const float2*)(rrb + (col & 1023));
                        split2(g_QWh + o, g_QWl + o, v0 + bw.x, v1 + bw.y);
                        split2(g_QRh + o, g_QRl + o, v0 + br.x, v1 + br.y);
                    } else if (sec == 1) {
                        split2(g_Kph + o, g_Kpl + o, v0, v1);
                    } else {
                        split2(g_Vph + o, g_Vpl + o, v0, v1);
                    }
                }
            } else {  // MODE 2: rk
                const int nh = col >> 6, d = col & 63;
#pragma unroll
                for (int rr = 0; rr < 2; rr++) {
                    const int row = row0 + rr * 8;
                    const float v0 = acc[i][j][rr * 2 + 0] + bz.x;
                    const float v1 = acc[i][j][rr * 2 + 1] + bz.y;
                    const size_t o = (((size_t)nh * QL + row) << 6) + d;
                    split2(g_Rph + o, g_Rpl + o, v0, v1);
                }
            }
        }
    }
}

// ---------------- MMA flash rel-attention (staged cp.async groups) ----------------
#define ATTM_SMEM 98304

__global__ __launch_bounds__(128) void attn_mma_kernel()
{
    extern __shared__ char sm[];
    const uint32_t sb = smem_u32(sm);
    const int it = blockIdx.x, n = blockIdx.y, b = blockIdx.z;
    const int i0 = it * 64;
    const int tid = threadIdx.x, w = tid >> 5, lane = tid & 31;
    const int q4 = lane & 3, g8 = lane >> 2;
    const int lrow = lane & 15, lhalf = lane >> 4;
    const size_t bn = (size_t)(b * NH + n) * QL;
    const size_t rn = (size_t)n * QL;

    const uint32_t uQ = sb;
    const uint32_t uKh = sb + 32768, uKl = uKh + 8192;
    const uint32_t uVh = uKl + 8192, uVl = uVh + 8192;
    const uint32_t uRh = sb + 65536, uRl = uRh + 16384;
    float* bdp = (float*)sm;  // sBD overlay on Q region: [64][128] fp32

#pragma unroll
    for (int k = 0; k < 4; k++) {
        int c = tid + k * 128;
        int row = c >> 3, ch = c & 7;
        size_t g = (bn + i0 + row) * 64 + ch * 8;
        uint32_t so = ASWZ(row, ch);
        cp16(uQ + so,         g_QWh + g);
        cp16(uQ + 8192 + so,  g_QWl + g);
        cp16(uQ + 16384 + so, g_QRh + g);
        cp16(uQ + 24576 + so, g_QRl + g);
    }
    cp_commit(); cp_wait0();
    __syncthreads();

    uint32_t qwh[4][4], qwl[4][4], qrh[4][4], qrl[4][4];
#pragma unroll
    for (int ks = 0; ks < 4; ks++) {
        uint32_t so = ASWZ(w * 16 + lrow, ks * 2 + lhalf);
        ldsm4(qwh[ks][0], qwh[ks][1], qwh[ks][2], qwh[ks][3], uQ + so);
        ldsm4(qwl[ks][0], qwl[ks][1], qwl[ks][2], qwl[ks][3], uQ + 8192 + so);
        ldsm4(qrh[ks][0], qrh[ks][1], qrh[ks][2], qrh[ks][3], uQ + 16384 + so);
        ldsm4(qrl[ks][0], qrl[ks][1], qrl[ks][2], qrl[ks][3], uQ + 24576 + so);
    }
    __syncthreads();  // Q smem now free -> sBD

    float oacc[8][4];
#pragma unroll
    for (int f = 0; f < 8; f++)
#pragma unroll
        for (int e = 0; e < 4; e++) oacc[f][e] = 0.f;
    float m0 = -1e30f, m1 = -1e30f, l0 = 0.f, l1 = 0.f;
    const int rb = 48 - w * 16;
    const int il0 = w * 16 + g8, il1 = il0 + 8;

    for (int jt = 0; jt <= it; jt++) {
        const int j0 = jt * 64;
        const int mb = j0 - i0 + 960;
        // ---- group 0: R tiles (consumed first, by BD) ----
#pragma unroll
        for (int k = 0; k < 8; k++) {
            int c = tid + k * 128;
            int row = c >> 3, ch = c & 7;
            int m = mb + row; if (m > 1023) m = 1023;
            size_t g = (rn + m) * 64 + ch * 8;
            uint32_t so = ASWZ(row, ch);
            cp16(uRh + so, g_Rph + g);
            cp16(uRl + so, g_Rpl + g);
        }
        cp_commit();
        // ---- group 1: K tiles (consumed by AC) ----
#pragma unroll
        for (int k = 0; k < 4; k++) {
            int c = tid + k * 128;
            int row = c >> 3, ch = c & 7;
            size_t g = (bn + j0 + row) * 64 + ch * 8;
            uint32_t so = ASWZ(row, ch);
            cp16(uKh + so, g_Kph + g);
            cp16(uKl + so, g_Kpl + g);
        }
        cp_commit();
        // ---- group 2: V tiles (consumed last, by PV) ----
#pragma unroll
        for (int k = 0; k < 4; k++) {
            int c = tid + k * 128;
            int row = c >> 3, ch = c & 7;
            size_t g = (bn + j0 + row) * 64 + ch * 8;
            uint32_t so = ASWZ(row, ch);
            cp16(uVh + so, g_Vph + g);
            cp16(uVl + so, g_Vpl + g);
        }
        cp_commit();

        cp_wait2();        // R resident (K,V still in flight)
        __syncthreads();

        // BD banded GEMM
        float bd[10][4];
#pragma unroll
        for (int f = 0; f < 10; f++)
#pragma unroll
            for (int e = 0; e < 4; e++) bd[f][e] = 0.f;
#pragma unroll
        for (int ks = 0; ks < 4; ks++) {
            uint32_t bh_[10][2], bl_[10][2];
#pragma unroll
            for (int g = 0; g < 5; g++) {
                uint32_t so = ASWZ(rb + g * 16 + lrow, ks * 2 + lhalf);
                uint32_t t0, t1, t2, t3;
                ldsm4(t0, t1, t2, t3, uRh + so);
                bh_[2 * g][0] = t0; bh_[2 * g][1] = t2;
                bh_[2 * g + 1][0] = t1; bh_[2 * g + 1][1] = t3;
                ldsm4(t0, t1, t2, t3, uRl + so);
                bl_[2 * g][0] = t0; bl_[2 * g][1] = t2;
                bl_[2 * g + 1][0] = t1; bl_[2 * g + 1][1] = t3;
            }
#pragma unroll
            for (int f = 0; f < 10; f++) {
                mma16816(bd[f], qrh[ks], bh_[f]);
                mma16816(bd[f], qrh[ks], bl_[f]);
                mma16816(bd[f], qrl[ks], bh_[f]);
            }
        }
        __syncwarp();
#pragma unroll
        for (int f = 0; f < 10; f++) {
            int col = rb + f * 8 + q4 * 2;
            *(float2*)(sm + ((w * 16 + g8) * 128 + col) * 4)     = make_float2(bd[f][0], bd[f][1]);
            *(float2*)(sm + ((w * 16 + g8 + 8) * 128 + col) * 4) = make_float2(bd[f][2], bd[f][3]);
        }
        __syncwarp();

        cp_wait1();        // K resident (V still in flight)
        __syncthreads();

        // AC GEMM
        float acc[8][4];
#pragma unroll
        for (int f = 0; f < 8; f++)
#pragma unroll
            for (int e = 0; e < 4; e++) acc[f][e] = 0.f;
#pragma unroll
        for (int ks = 0; ks < 4; ks++) {
            uint32_t kh_[8][2], kl_[8][2];
#pragma unroll
            for (int g = 0; g < 4; g++) {
                uint32_t so = ASWZ(g * 16 + lrow, ks * 2 + lhalf);
                uint32_t t0, t1, t2, t3;
                ldsm4(t0, t1, t2, t3, uKh + so);
                kh_[2 * g][0] = t0; kh_[2 * g][1] = t2;
                kh_[2 * g + 1][0] = t1; kh_[2 * g + 1][1] = t3;
                ldsm4(t0, t1, t2, t3, uKl + so);
                kl_[2 * g][0] = t0; kl_[2 * g][1] = t2;
                kl_[2 * g + 1][0] = t1; kl_[2 * g + 1][1] = t3;
            }
#pragma unroll
            for (int f = 0; f < 8; f++) {
                mma16816(acc[f], qwh[ks], kh_[f]);
                mma16816(acc[f], qwh[ks], kl_[f]);
                mma16816(acc[f], qwl[ks], kh_[f]);
            }
        }

        // softmax on fragments
        const bool diag = (jt == it);
        float mx0 = -1e30f, mx1 = -1e30f;
#pragma unroll
        for (int f = 0; f < 8; f++) {
#pragma unroll
            for (int e = 0; e < 4; e++) {
                int jl = f * 8 + q4 * 2 + (e & 1);
                int il = (e < 2) ? il0 : il1;
                float sv = (acc[f][e] + bdp[il * 128 + (jl - il + 63)]) * ATT_SCALE;
                if (diag && jl > il) sv = -1e30f;
                acc[f][e] = sv;
            }
            mx0 = fmaxf(mx0, fmaxf(acc[f][0], acc[f][1]));
            mx1 = fmaxf(mx1, fmaxf(acc[f][2], acc[f][3]));
        }
        mx0 = fmaxf(mx0, __shfl_xor_sync(0xffffffffu, mx0, 1));
        mx0 = fmaxf(mx0, __shfl_xor_sync(0xffffffffu, mx0, 2));
        mx1 = fmaxf(mx1, __shfl_xor_sync(0xffffffffu, mx1, 1));
        mx1 = fmaxf(mx1, __shfl_xor_sync(0xffffffffu, mx1, 2));
        float mn0 = fmaxf(m0, mx0), mn1 = fmaxf(m1, mx1);
        float al0 = __expf(m0 - mn0), al1 = __expf(m1 - mn1);
        m0 = mn0; m1 = mn1;

        float rs0 = 0.f, rs1 = 0.f;
        uint32_t pah[4][4], pal[4][4];
#pragma unroll
        for (int f = 0; f < 8; f++) {
            float p0 = __expf(acc[f][0] - mn0), p1 = __expf(acc[f][1] - mn0);
            float p2 = __expf(acc[f][2] - mn1), p3 = __expf(acc[f][3] - mn1);
            rs0 += p0 + p1; rs1 += p2 + p3;
            __nv_bfloat16 h0 = __float2bfloat16(p0), h1 = __float2bfloat16(p1);
            __nv_bfloat16 h2 = __float2bfloat16(p2), h3 = __float2bfloat16(p3);
            uint32_t uh01, uh23, ul01, ul23;
            *(__nv_bfloat162*)&uh01 = __halves2bfloat162(h0, h1);
            *(__nv_bfloat162*)&uh23 = __halves2bfloat162(h2, h3);
            ul01 = packbf(p0 - __bfloat162float(h0), p1 - __bfloat162float(h1));
            ul23 = packbf(p2 - __bfloat162float(h2), p3 - __bfloat162float(h3));
            int kb = f >> 1;
            if ((f & 1) == 0) { pah[kb][0] = uh01; pah[kb][1] = uh23;
                                pal[kb][0] = ul01; pal[kb][1] = ul23; }
            else              { pah[kb][2] = uh01; pah[kb][3] = uh23;
                                pal[kb][2] = ul01; pal[kb][3] = ul23; }
        }
        rs0 += __shfl_xor_sync(0xffffffffu, rs0, 1);
        rs0 += __shfl_xor_sync(0xffffffffu, rs0, 2);
        rs1 += __shfl_xor_sync(0xffffffffu, rs1, 1);
        rs1 += __shfl_xor_sync(0xffffffffu, rs1, 2);
        l0 = l0 * al0 + rs0;
        l1 = l1 * al1 + rs1;
#pragma unroll
        for (int f = 0; f < 8; f++) {
            oacc[f][0] *= al0; oacc[f][1] *= al0;
            oacc[f][2] *= al1; oacc[f][3] *= al1;
        }

        cp_wait0();        // V resident
        __syncthreads();

        // PV
#pragma unroll
        for (int kb = 0; kb < 4; kb++) {
            uint32_t vh_[8][2], vl_[8][2];
#pragma unroll
            for (int g = 0; g < 4; g++) {
                uint32_t so = ASWZ(kb * 16 + lrow, g * 2 + lhalf);
                uint32_t t0, t1, t2, t3;
                ldsm4t(t0, t1, t2, t3, uVh + so);
                vh_[2 * g][0] = t0; vh_[2 * g][1] = t1;
                vh_[2 * g + 1][0] = t2; vh_[2 * g + 1][1] = t3;
                ldsm4t(t0, t1, t2, t3, uVl + so);
                vl_[2 * g][0] = t0; vl_[2 * g][1] = t1;
                vl_[2 * g + 1][0] = t2; vl_[2 * g + 1][1] = t3;
            }
#pragma unroll
            for (int f = 0; f < 8; f++) {
                mma16816(oacc[f], pah[kb], vh_[f]);
                mma16816(oacc[f], pal[kb], vh_[f]);
                mma16816(oacc[f], pah[kb], vl_[f]);
            }
        }
        __syncthreads();   // all reads done before next iter's loads overwrite
    }

    // epilogue: split-store directly into vec_hi/vec_lo
    float inv0 = 1.f / l0, inv1 = 1.f / l1;
    int gi0 = i0 + il0, gi1 = i0 + il1;
#pragma unroll
    for (int f = 0; f < 8; f++) {
        int d = f * 8 + q4 * 2;
        size_t o0 = ((size_t)gi0 * BSZ + b) * HD + n * 64 + d;
        size_t o1 = ((size_t)gi1 * BSZ + b) * HD + n * 64 + d;
        split2(g_vec_hi + o0, g_vec_lo + o0, oacc[f][0] * inv0, oacc[f][1] * inv0);
        split2(g_vec_hi + o1, g_vec_lo + o1, oacc[f][2] * inv1, oacc[f][3] * inv1);
    }
}

// ---------------- residual + LayerNorm ----------------
__global__ __launch_bounds__(256) void ln_kernel(
    const float* __restrict__ w, const float* __restrict__ ao,
    const float* __restrict__ g, const float* __restrict__ bb,
    float* __restrict__ out)
{
    __shared__ float red[8];
    __shared__ float s_mu, s_rstd;
    const int row = blockIdx.x;
    const int tid = threadIdx.x;
    const int lane = tid & 31, wid = tid >> 5;
    const size_t base = (size_t)row * DM + tid * 4;

    float4 wv = *(const float4*)(w + base);
    float4 av = *(const float4*)(ao + base);
    float x0 = wv.x + av.x, x1 = wv.y + av.y, x2 = wv.z + av.z, x3 = wv.w + av.w;

    float s = x0 + x1 + x2 + x3;
#pragma unroll
    for (int o = 16; o >= 1; o >>= 1) s += __shfl_xor_sync(0xffffffffu, s, o);
    if (lane == 0) red[wid] = s;
    __syncthreads();
    if (tid == 0) {
        float t = 0.f;
#pragma unroll
        for (int i = 0; i < 8; i++) t += red[i];
        s_mu = t * (1.0f / DM);
    }
    __syncthreads();
    const float mu = s_mu;

    float d0 = x0 - mu, d1 = x1 - mu, d2 = x2 - mu, d3 = x3 - mu;
    float ss = d0 * d0 + d1 * d1 + d2 * d2 + d3 * d3;
#pragma unroll
    for (int o = 16; o >= 1; o >>= 1) ss += __shfl_xor_sync(0xffffffffu, ss, o);
    if (lane == 0) red[wid] = ss;
    __syncthreads();
    if (tid == 0) {
        float t = 0.f;
#pragma unroll
        for (int i = 0; i < 8; i++) t += red[i];
        s_rstd = rsqrtf(t * (1.0f / DM) + 1e-5f);
    }
    __syncthreads();
    const float rstd = s_rstd;

    float4 gv = *(const float4*)(g + tid * 4);
    float4 bv = *(const float4*)(bb + tid * 4);
    float4 o4;
    o4.x = d0 * rstd * gv.x + bv.x;
    o4.y = d1 * rstd * gv.y + bv.y;
    o4.z = d2 * rstd * gv.z + bv.z;
    o4.w = d3 * rstd * gv.w + bv.w;
    *(float4*)(out + base) = o4;
}

// ---------------- launch ----------------
extern "C" void kernel_launch(void* const* d_in, const int* in_sizes, int n_in,
                              void* d_out, int out_size)
{
    (void)in_sizes; (void)n_in; (void)out_size;
    const float* w     = (const float*)d_in[0];
    const float* r     = (const float*)d_in[1];
    const float* rwb   = (const float*)d_in[2];
    const float* rrb   = (const float*)d_in[3];
    const float* qkv_w = (const float*)d_in[4];
    const float* qkv_b = (const float*)d_in[5];
    const float* rk_w  = (const float*)d_in[6];
    const float* rk_b  = (const float*)d_in[7];
    const float* o_w   = (const float*)d_in[8];
    const float* o_b   = (const float*)d_in[9];
    const float* ln_g  = (const float*)d_in[10];
    const float* ln_b  = (const float*)d_in[11];
    float* out = (float*)d_out;

    float* ao;
    cudaGetSymbolAddress((void**)&ao, g_ao);
    __nv_bfloat16 *w_hi, *w_lo, *r_hi, *r_lo, *vec_hi, *vec_lo;
    __nv_bfloat16 *qkvwT_hi, *qkvwT_lo, *rkwT_hi, *rkwT_lo, *owT_hi, *owT_lo;
    cudaGetSymbolAddress((void**)&w_hi, g_w_hi);
    cudaGetSymbolAddress((void**)&w_lo, g_w_lo);
    cudaGetSymbolAddress((void**)&r_hi, g_r_hi);
    cudaGetSymbolAddress((void**)&r_lo, g_r_lo);
    cudaGetSymbolAddress((void**)&vec_hi, g_vec_hi);
    cudaGetSymbolAddress((void**)&vec_lo, g_vec_lo);
    cudaGetSymbolAddress((void**)&qkvwT_hi, g_qkvwT_hi);
    cudaGetSymbolAddress((void**)&qkvwT_lo, g_qkvwT_lo);
    cudaGetSymbolAddress((void**)&rkwT_hi, g_rkwT_hi);
    cudaGetSymbolAddress((void**)&rkwT_lo, g_rkwT_lo);
    cudaGetSymbolAddress((void**)&owT_hi, g_owT_hi);
    cudaGetSymbolAddress((void**)&owT_lo, g_owT_lo);

    cudaFuncSetAttribute(gemm_fused_kernel<0>, cudaFuncAttributeMaxDynamicSharedMemorySize, GSMEM);
    cudaFuncSetAttribute(gemm_fused_kernel<1>, cudaFuncAttributeMaxDynamicSharedMemorySize, GSMEM);
    cudaFuncSetAttribute(gemm_fused_kernel<2>, cudaFuncAttributeMaxDynamicSharedMemorySize, GSMEM);
    cudaFuncSetAttribute(attn_mma_kernel, cudaFuncAttributeMaxDynamicSharedMemorySize, ATTM_SMEM);

    // idx 0-2: conversions needed for QKV GEMM
    split_kernel<<<(NROWS * DM / 4 + 255) / 256, 256>>>(
        (const float4*)w, (__nv_bfloat162*)w_hi, (__nv_bfloat162*)w_lo, NROWS * DM / 4);
    split_kernel<<<(QL * DM / 4 + 255) / 256, 256>>>(
        (const float4*)r, (__nv_bfloat162*)r_hi, (__nv_bfloat162*)r_lo, QL * DM / 4);
    transpose_split_kernel<<<dim3(QKV3 / 32, DM / 32), 256>>>(qkv_w, qkvwT_hi, qkvwT_lo, DM, QKV3);

    // idx 3 (ncu capture slot): QKV GEMM with fused repack epilogue
    gemm_fused_kernel<1><<<dim3(QKV3 / 128, NROWS / 128), 256, GSMEM>>>(
        w_hi, w_lo, qkvwT_hi, qkvwT_lo, qkv_b, nullptr, rwb, rrb, NROWS, QKV3, DM);

    // rk GEMM with fused repack epilogue
    transpose_split_kernel<<<dim3(HD / 32, DM / 32), 256>>>(rk_w, rkwT_hi, rkwT_lo, DM, HD);
    gemm_fused_kernel<2><<<dim3(HD / 128, QL / 128), 256, GSMEM>>>(
        r_hi, r_lo, rkwT_hi, rkwT_lo, rk_b, nullptr, nullptr, nullptr, QL, HD, DM);

    // fused MMA rel-attention (writes split vec directly)
    attn_mma_kernel<<<dim3(QL / 64, NH, BSZ), 128, ATTM_SMEM>>>();

    // out-proj
    transpose_split_kernel<<<dim3(DM / 32, HD / 32), 256>>>(o_w, owT_hi, owT_lo, HD, DM);
    gemm_fused_kernel<0><<<dim3(DM / 128, NROWS / 128), 256, GSMEM>>>(
        vec_hi, vec_lo, owT_hi, owT_lo, o_b, ao, nullptr, nullptr, NROWS, DM, DM);

    // residual + LayerNorm
    ln_kernel<<<NROWS, 256>>>(w, ao, ln_g, ln_b, out);
}

// round 15
// speedup vs baseline: 1.1970x; 1.0883x over previous
#include <cuda_runtime.h>
#include <cuda_bf16.h>
#include <cstdint>

#define QL   1024
#define BSZ  4
#define DM   1024
#define NH   16
#define DH   64
#define HD   1024      // NH*DH
#define QKV3 3072
#define NROWS (QL*BSZ) // 4096
#define ATT_SCALE 0.125f

// ---------------- scratch (no allocation allowed) ----------------
__device__ __align__(16) float g_ao[(size_t)NROWS * DM];

// split-bf16 GEMM operands
__device__ __align__(16) __nv_bfloat16 g_w_hi[(size_t)NROWS * DM];
__device__ __align__(16) __nv_bfloat16 g_w_lo[(size_t)NROWS * DM];
__device__ __align__(16) __nv_bfloat16 g_r_hi[(size_t)QL * DM];
__device__ __align__(16) __nv_bfloat16 g_r_lo[(size_t)QL * DM];
__device__ __align__(16) __nv_bfloat16 g_vec_hi[(size_t)NROWS * HD];
__device__ __align__(16) __nv_bfloat16 g_vec_lo[(size_t)NROWS * HD];
__device__ __align__(16) __nv_bfloat16 g_qkvwT_hi[(size_t)QKV3 * DM];
__device__ __align__(16) __nv_bfloat16 g_qkvwT_lo[(size_t)QKV3 * DM];
__device__ __align__(16) __nv_bfloat16 g_rkwT_hi[(size_t)HD * DM];
__device__ __align__(16) __nv_bfloat16 g_rkwT_lo[(size_t)HD * DM];
__device__ __align__(16) __nv_bfloat16 g_owT_hi[(size_t)DM * HD];
__device__ __align__(16) __nv_bfloat16 g_owT_lo[(size_t)DM * HD];

// attention repacked operands: [b][n][row][64] bf16 (written by GEMM epilogues)
__device__ __align__(16) __nv_bfloat16 g_QWh[(size_t)NROWS * HD];
__device__ __align__(16) __nv_bfloat16 g_QWl[(size_t)NROWS * HD];
__device__ __align__(16) __nv_bfloat16 g_QRh[(size_t)NROWS * HD];
__device__ __align__(16) __nv_bfloat16 g_QRl[(size_t)NROWS * HD];
__device__ __align__(16) __nv_bfloat16 g_Kph[(size_t)NROWS * HD];
__device__ __align__(16) __nv_bfloat16 g_Kpl[(size_t)NROWS * HD];
__device__ __align__(16) __nv_bfloat16 g_Vph[(size_t)NROWS * HD];
__device__ __align__(16) __nv_bfloat16 g_Vpl[(size_t)NROWS * HD];
__device__ __align__(16) __nv_bfloat16 g_Rph[(size_t)NH * QL * DH];
__device__ __align__(16) __nv_bfloat16 g_Rpl[(size_t)NH * QL * DH];

// ---------------- PTX helpers ----------------
__device__ __forceinline__ uint32_t smem_u32(const void* p) {
    uint32_t a;
    asm("{ .reg .u64 t; cvta.to.shared.u64 t, %1; cvt.u32.u64 %0, t; }" : "=r"(a) : "l"(p));
    return a;
}
__device__ __forceinline__ void cp16(uint32_t s, const void* g) {
    asm volatile("cp.async.cg.shared.global [%0], [%1], 16;" :: "r"(s), "l"(g));
}
__device__ __forceinline__ void cp_commit() {
    asm volatile("cp.async.commit_group;" ::: "memory");
}
__device__ __forceinline__ void cp_wait0() {
    asm volatile("cp.async.wait_group 0;" ::: "memory");
}
__device__ __forceinline__ void cp_wait1() {
    asm volatile("cp.async.wait_group 1;" ::: "memory");
}
__device__ __forceinline__ void cp_wait2() {
    asm volatile("cp.async.wait_group 2;" ::: "memory");
}
__device__ __forceinline__ void ldsm4(uint32_t& r0, uint32_t& r1, uint32_t& r2, uint32_t& r3,
                                      uint32_t a) {
    asm volatile("ldmatrix.sync.aligned.m8n8.x4.shared.b16 {%0,%1,%2,%3}, [%4];"
                 : "=r"(r0), "=r"(r1), "=r"(r2), "=r"(r3) : "r"(a));
}
__device__ __forceinline__ void ldsm4t(uint32_t& r0, uint32_t& r1, uint32_t& r2, uint32_t& r3,
                                       uint32_t a) {
    asm volatile("ldmatrix.sync.aligned.m8n8.x4.trans.shared.b16 {%0,%1,%2,%3}, [%4];"
                 : "=r"(r0), "=r"(r1), "=r"(r2), "=r"(r3) : "r"(a));
}
__device__ __forceinline__ void mma16816(float* d, const uint32_t* a, const uint32_t* b) {
    asm volatile("mma.sync.aligned.m16n8k16.row.col.f32.bf16.bf16.f32 "
                 "{%0,%1,%2,%3}, {%4,%5,%6,%7}, {%8,%9}, {%0,%1,%2,%3};"
                 : "+f"(d[0]), "+f"(d[1]), "+f"(d[2]), "+f"(d[3])
                 : "r"(a[0]), "r"(a[1]), "r"(a[2]), "r"(a[3]), "r"(b[0]), "r"(b[1]));
}
__device__ __forceinline__ uint32_t packbf(float a, float b) {
    __nv_bfloat162 t = __halves2bfloat162(__float2bfloat16(a), __float2bfloat16(b));
    uint32_t u;
    *(__nv_bfloat162*)&u = t;
    return u;
}
__device__ __forceinline__ void split2(__nv_bfloat16* hi, __nv_bfloat16* lo, float a, float b) {
    __nv_bfloat16 h0 = __float2bfloat16(a), h1 = __float2bfloat16(b);
    *(__nv_bfloat162*)hi = __halves2bfloat162(h0, h1);
    *(__nv_bfloat162*)lo = __halves2bfloat162(
        __float2bfloat16(a - __bfloat162float(h0)),
        __float2bfloat16(b - __bfloat162float(h1)));
}

// swizzled byte offset for [rows][64 bf16] tiles (128B rows)
#define ASWZ(row, ch) ((uint32_t)((row) * 128 + ((((ch) ^ ((row) & 7))) << 4)))

// ---------------- merged prep: splits + transpose-splits, one launch -----------
// blocks [0,4096): split w   [4096,5120): split r
// [5120,8192): transpose qkv_w   [8192,9216): transpose rk_w   [9216,10240): o_w
#define PREP_BLOCKS 10240

__device__ __forceinline__ void split_quad(const float4* x, __nv_bfloat162* hi,
                                           __nv_bfloat162* lo, int i)
{
    float4 v = x[i];
    __nv_bfloat16 h0 = __float2bfloat16(v.x);
    __nv_bfloat16 h1 = __float2bfloat16(v.y);
    __nv_bfloat16 h2 = __float2bfloat16(v.z);
    __nv_bfloat16 h3 = __float2bfloat16(v.w);
    hi[2 * i]     = __halves2bfloat162(h0, h1);
    hi[2 * i + 1] = __halves2bfloat162(h2, h3);
    lo[2 * i]     = __halves2bfloat162(
        __float2bfloat16(v.x - __bfloat162float(h0)),
        __float2bfloat16(v.y - __bfloat162float(h1)));
    lo[2 * i + 1] = __halves2bfloat162(
        __float2bfloat16(v.z - __bfloat162float(h2)),
        __float2bfloat16(v.w - __bfloat162float(h3)));
}

__global__ __launch_bounds__(256) void prep_kernel(
    const float* __restrict__ w, const float* __restrict__ r,
    const float* __restrict__ qkv_w, const float* __restrict__ rk_w,
    const float* __restrict__ o_w)
{
    __shared__ float ts[32][33];
    const int bx = blockIdx.x, tid = threadIdx.x;
    if (bx < 4096) {
        split_quad((const float4*)w, (__nv_bfloat162*)g_w_hi, (__nv_bfloat162*)g_w_lo,
                   bx * 256 + tid);
        return;
    }
    if (bx < 5120) {
        split_quad((const float4*)r, (__nv_bfloat162*)g_r_hi, (__nv_bfloat162*)g_r_lo,
                   (bx - 4096) * 256 + tid);
        return;
    }
    const float* W;
    __nv_bfloat16 *Th, *Tl;
    int K, N, k0, n0;
    if (bx < 8192) {
        int i = bx - 5120;
        W = qkv_w; Th = g_qkvwT_hi; Tl = g_qkvwT_lo; K = DM; N = QKV3;
        n0 = (i % 96) * 32; k0 = (i / 96) * 32;
    } else if (bx < 9216) {
        int i = bx - 8192;
        W = rk_w; Th = g_rkwT_hi; Tl = g_rkwT_lo; K = DM; N = HD;
        n0 = (i % 32) * 32; k0 = (i / 32) * 32;
    } else {
        int i = bx - 9216;
        W = o_w; Th = g_owT_hi; Tl = g_owT_lo; K = HD; N = DM;
        n0 = (i % 32) * 32; k0 = (i / 32) * 32;
    }
    const int tx = tid & 31, ty = tid >> 5;
#pragma unroll
    for (int rr = ty; rr < 32; rr += 8)
        ts[rr][tx] = W[(size_t)(k0 + rr) * N + n0 + tx];
    __syncthreads();
#pragma unroll
    for (int rr = ty; rr < 32; rr += 8) {
        float x = ts[tx][rr];
        __nv_bfloat16 h = __float2bfloat16(x);
        __nv_bfloat16 l = __float2bfloat16(x - __bfloat162float(h));
        size_t o = (size_t)(n0 + rr) * K + k0 + tx;
        Th[o] = h;
        Tl[o] = l;
    }
}

// ---------------- GEMM tiles / pipeline constants ----------------
#define GBK 32
#define GT_BYTES (128 * GBK * 2)
#define GSTAGE   (4 * GT_BYTES)
#define GSMEM    (3 * GSTAGE)     // 3 stages = 98304
#define QKV_CTAS 768              // (QKV3/128)*(NROWS/128)

__device__ __forceinline__ uint32_t gswz(int row, int ch) {
    return (uint32_t)(row * 64 + ((ch ^ ((row >> 1) & 3)) << 4));
}

// ---- shared mainloop for K=1024 split-bf16 GEMM, 3-stage pipeline ----
__device__ __forceinline__ void gemm_mainloop_k1024(
    const __nv_bfloat16* Ahi, const __nv_bfloat16* Alo,
    const __nv_bfloat16* Bhi, const __nv_bfloat16* Blo,
    int m0, int n0, uint32_t sb, int tid, float acc[2][8][4])
{
    const int wid = tid >> 5, lane = tid & 31;
    const int wm = wid >> 1, wn = wid & 1;
    const int r0 = tid >> 2, c0 = tid & 3;
    const int r1 = (tid + 256) >> 2, c1 = tid & 3;
    const int lrow = lane & 15, lkh = lane >> 4;
    const int kiters = 1024 / GBK;  // 32

    auto load_stage = [&](int stg, int k0) {
        const uint32_t st = sb + stg * GSTAGE;
        const uint32_t o0 = gswz(r0, c0), o1 = gswz(r1, c1);
        const size_t ga0 = (size_t)(m0 + r0) * 1024 + k0 + c0 * 8;
        const size_t ga1 = (size_t)(m0 + r1) * 1024 + k0 + c1 * 8;
        const size_t gb0 = (size_t)(n0 + r0) * 1024 + k0 + c0 * 8;
        const size_t gb1 = (size_t)(n0 + r1) * 1024 + k0 + c1 * 8;
        cp16(st + o0,                Ahi + ga0);
        cp16(st + o1,                Ahi + ga1);
        cp16(st + GT_BYTES + o0,     Alo + ga0);
        cp16(st + GT_BYTES + o1,     Alo + ga1);
        cp16(st + 2 * GT_BYTES + o0, Bhi + gb0);
        cp16(st + 2 * GT_BYTES + o1, Bhi + gb1);
        cp16(st + 3 * GT_BYTES + o0, Blo + gb0);
        cp16(st + 3 * GT_BYTES + o1, Blo + gb1);
        cp_commit();
    };

    load_stage(0, 0);
    load_stage(1, GBK);

    int stg = 0;
    for (int c = 0; c < kiters; ++c) {
        if (c + 1 < kiters) cp_wait1(); else cp_wait0();
        __syncthreads();
        if (c + 2 < kiters) {
            int nxt = stg + 2; if (nxt >= 3) nxt -= 3;
            load_stage(nxt, (c + 2) * GBK);
        }
        const uint32_t st = sb + stg * GSTAGE;
#pragma unroll
        for (int s = 0; s < 2; ++s) {
            const int ch = s * 2 + lkh;
            uint32_t ah[2][4], al[2][4];
#pragma unroll
            for (int i = 0; i < 2; i++) {
                const int row = wm * 32 + i * 16 + lrow;
                const uint32_t o = gswz(row, ch);
                ldsm4(ah[i][0], ah[i][1], ah[i][2], ah[i][3], st + o);
                ldsm4(al[i][0], al[i][1], al[i][2], al[i][3], st + GT_BYTES + o);
            }
            uint32_t bh[8][2], bl[8][2];
#pragma unroll
            for (int g = 0; g < 4; g++) {
                const int row = wn * 64 + g * 16 + lrow;
                const uint32_t o = gswz(row, ch);
                uint32_t t0, t1, t2, t3;
                ldsm4(t0, t1, t2, t3, st + 2 * GT_BYTES + o);
                bh[2 * g][0] = t0; bh[2 * g][1] = t2;
                bh[2 * g + 1][0] = t1; bh[2 * g + 1][1] = t3;
                ldsm4(t0, t1, t2, t3, st + 3 * GT_BYTES + o);
                bl[2 * g][0] = t0; bl[2 * g][1] = t2;
                bl[2 * g + 1][0] = t1; bl[2 * g + 1][1] = t3;
            }
#pragma unroll
            for (int i = 0; i < 2; i++)
#pragma unroll
                for (int j = 0; j < 8; j++) {
                    mma16816(acc[i][j], ah[i], bh[j]);
                    mma16816(acc[i][j], ah[i], bl[j]);
                    mma16816(acc[i][j], al[i], bh[j]);
                }
        }
        stg = (stg == 2) ? 0 : stg + 1;
    }
}

// ---- merged QKV + rk GEMM: bx<768 -> QKV repack epilogue, else rk repack ----
__global__ __launch_bounds__(256, 2) void gemm_qkv_rk_kernel(
    const float* __restrict__ qkv_b, const float* __restrict__ rk_b,
    const float* __restrict__ rwb, const float* __restrict__ rrb)
{
    extern __shared__ char smem[];
    const uint32_t sb = smem_u32(smem);
    const int tid = threadIdx.x;
    const int bx = blockIdx.x;
    const bool isqkv = bx < QKV_CTAS;

    const __nv_bfloat16 *Ahi, *Alo, *Bhi, *Blo;
    const float* bias;
    int m0, n0;
    if (isqkv) {
        m0 = (bx / 24) * 128; n0 = (bx % 24) * 128;
        Ahi = g_w_hi; Alo = g_w_lo; Bhi = g_qkvwT_hi; Blo = g_qkvwT_lo;
        bias = qkv_b;
    } else {
        int i = bx - QKV_CTAS;
        m0 = (i / 8) * 128; n0 = (i % 8) * 128;
        Ahi = g_r_hi; Alo = g_r_lo; Bhi = g_rkwT_hi; Blo = g_rkwT_lo;
        bias = rk_b;
    }

    float acc[2][8][4];
#pragma unroll
    for (int i = 0; i < 2; i++)
#pragma unroll
        for (int j = 0; j < 8; j++)
#pragma unroll
            for (int t = 0; t < 4; t++) acc[i][j][t] = 0.f;

    gemm_mainloop_k1024(Ahi, Alo, Bhi, Blo, m0, n0, sb, tid, acc);

    const int wid = tid >> 5, lane = tid & 31;
    const int wm = wid >> 1, wn = wid & 1;
    const int sec = n0 >> 10;
#pragma unroll
    for (int i = 0; i < 2; i++) {
        const int row0 = m0 + wm * 32 + i * 16 + (lane >> 2);
#pragma unroll
        for (int j = 0; j < 8; j++) {
            const int col = n0 + wn * 64 + j * 8 + (lane & 3) * 2;
            const float2 bz = *(const float2*)(bias + col);
            if (isqkv) {
                const int nh = (col & 1023) >> 6;
                const int d  = col & 63;
#pragma unroll
                for (int rr = 0; rr < 2; rr++) {
                    const int row = row0 + rr * 8;
                    const float v0 = acc[i][j][rr * 2 + 0] + bz.x;
                    const float v1 = acc[i][j][rr * 2 + 1] + bz.y;
                    const int qi = row >> 2, bb = row & 3;
                    const size_t o = (((size_t)(bb * NH + nh) * QL + qi) << 6) + d;
                    if (sec == 0) {
                        const float2 bw = *(const float2*)(rwb + (col & 1023));
                        const float2 br = *(const float2*)(rrb + (col & 1023));
                        split2(g_QWh + o, g_QWl + o, v0 + bw.x, v1 + bw.y);
                        split2(g_QRh + o, g_QRl + o, v0 + br.x, v1 + br.y);
                    } else if (sec == 1) {
                        split2(g_Kph + o, g_Kpl + o, v0, v1);
                    } else {
                        split2(g_Vph + o, g_Vpl + o, v0, v1);
                    }
                }
            } else {
                const int nh = col >> 6, d = col & 63;
#pragma unroll
                for (int rr = 0; rr < 2; rr++) {
                    const int row = row0 + rr * 8;
                    const float v0 = acc[i][j][rr * 2 + 0] + bz.x;
                    const float v1 = acc[i][j][rr * 2 + 1] + bz.y;
                    const size_t o = (((size_t)nh * QL + row) << 6) + d;
                    split2(g_Rph + o, g_Rpl + o, v0, v1);
                }
            }
        }
    }
}

// ---- out-projection GEMM: C = vec @ o_w^T + bias (fp32 out) ----
__global__ __launch_bounds__(256, 2) void gemm_out_kernel(
    const float* __restrict__ bias, float* __restrict__ C)
{
    extern __shared__ char smem[];
    const uint32_t sb = smem_u32(smem);
    const int tid = threadIdx.x;
    const int m0 = blockIdx.y * 128;
    const int n0 = blockIdx.x * 128;

    float acc[2][8][4];
#pragma unroll
    for (int i = 0; i < 2; i++)
#pragma unroll
        for (int j = 0; j < 8; j++)
#pragma unroll
            for (int t = 0; t < 4; t++) acc[i][j][t] = 0.f;

    gemm_mainloop_k1024(g_vec_hi, g_vec_lo, g_owT_hi, g_owT_lo, m0, n0, sb, tid, acc);

    const int wid = tid >> 5, lane = tid & 31;
    const int wm = wid >> 1, wn = wid & 1;
#pragma unroll
    for (int i = 0; i < 2; i++) {
        const int row0 = m0 + wm * 32 + i * 16 + (lane >> 2);
#pragma unroll
        for (int j = 0; j < 8; j++) {
            const int col = n0 + wn * 64 + j * 8 + (lane & 3) * 2;
            const float2 bz = *(const float2*)(bias + col);
            float2 v0, v1;
            v0.x = acc[i][j][0] + bz.x; v0.y = acc[i][j][1] + bz.y;
            v1.x = acc[i][j][2] + bz.x; v1.y = acc[i][j][3] + bz.y;
            *(float2*)(C + (size_t)row0 * DM + col)       = v0;
            *(float2*)(C + (size_t)(row0 + 8) * DM + col) = v1;
        }
    }
}

// ---------------- MMA flash rel-attention (staged cp.async groups) ----------------
#define ATTM_SMEM 98304

__global__ __launch_bounds__(128) void attn_mma_kernel()
{
    extern __shared__ char sm[];
    const uint32_t sb = smem_u32(sm);
    const int it = 15 - (int)blockIdx.x;   // longest CTAs scheduled first
    const int n = blockIdx.y, b = blockIdx.z;
    const int i0 = it * 64;
    const int tid = threadIdx.x, w = tid >> 5, lane = tid & 31;
    const int q4 = lane & 3, g8 = lane >> 2;
    const int lrow = lane & 15, lhalf = lane >> 4;
    const size_t bn = (size_t)(b * NH + n) * QL;
    const size_t rn = (size_t)n * QL;

    const uint32_t uQ = sb;
    const uint32_t uKh = sb + 32768, uKl = uKh + 8192;
    const uint32_t uVh = uKl + 8192, uVl = uVh + 8192;
    const uint32_t uRh = sb + 65536, uRl = uRh + 16384;
    float* bdp = (float*)sm;  // sBD overlay on Q region: [64][128] fp32

#pragma unroll
    for (int k = 0; k < 4; k++) {
        int c = tid + k * 128;
        int row = c >> 3, ch = c & 7;
        size_t g = (bn + i0 + row) * 64 + ch * 8;
        uint32_t so = ASWZ(row, ch);
        cp16(uQ + so,         g_QWh + g);
        cp16(uQ + 8192 + so,  g_QWl + g);
        cp16(uQ + 16384 + so, g_QRh + g);
        cp16(uQ + 24576 + so, g_QRl + g);
    }
    cp_commit(); cp_wait0();
    __syncthreads();

    uint32_t qwh[4][4], qwl[4][4], qrh[4][4], qrl[4][4];
#pragma unroll
    for (int ks = 0; ks < 4; ks++) {
        uint32_t so = ASWZ(w * 16 + lrow, ks * 2 + lhalf);
        ldsm4(qwh[ks][0], qwh[ks][1], qwh[ks][2], qwh[ks][3], uQ + so);
        ldsm4(qwl[ks][0], qwl[ks][1], qwl[ks][2], qwl[ks][3], uQ + 8192 + so);
        ldsm4(qrh[ks][0], qrh[ks][1], qrh[ks][2], qrh[ks][3], uQ + 16384 + so);
        ldsm4(qrl[ks][0], qrl[ks][1], qrl[ks][2], qrl[ks][3], uQ + 24576 + so);
    }
    __syncthreads();  // Q smem now free -> sBD

    float oacc[8][4];
#pragma unroll
    for (int f = 0; f < 8; f++)
#pragma unroll
        for (int e = 0; e < 4; e++) oacc[f][e] = 0.f;
    float m0 = -1e30f, m1 = -1e30f, l0 = 0.f, l1 = 0.f;
    const int rb = 48 - w * 16;
    const int il0 = w * 16 + g8, il1 = il0 + 8;

    for (int jt = 0; jt <= it; jt++) {
        const int j0 = jt * 64;
        const int mb = j0 - i0 + 960;
#pragma unroll
        for (int k = 0; k < 8; k++) {
            int c = tid + k * 128;
            int row = c >> 3, ch = c & 7;
            int m = mb + row; if (m > 1023) m = 1023;
            size_t g = (rn + m) * 64 + ch * 8;
            uint32_t so = ASWZ(row, ch);
            cp16(uRh + so, g_Rph + g);
            cp16(uRl + so, g_Rpl + g);
        }
        cp_commit();
#pragma unroll
        for (int k = 0; k < 4; k++) {
            int c = tid + k * 128;
            int row = c >> 3, ch = c & 7;
            size_t g = (bn + j0 + row) * 64 + ch * 8;
            uint32_t so = ASWZ(row, ch);
            cp16(uKh + so, g_Kph + g);
            cp16(uKl + so, g_Kpl + g);
        }
        cp_commit();
#pragma unroll
        for (int k = 0; k < 4; k++) {
            int c = tid + k * 128;
            int row = c >> 3, ch = c & 7;
            size_t g = (bn + j0 + row) * 64 + ch * 8;
            uint32_t so = ASWZ(row, ch);
            cp16(uVh + so, g_Vph + g);
            cp16(uVl + so, g_Vpl + g);
        }
        cp_commit();

        cp_wait2();
        __syncthreads();

        // BD banded GEMM
        float bd[10][4];
#pragma unroll
        for (int f = 0; f < 10; f++)
#pragma unroll
            for (int e = 0; e < 4; e++) bd[f][e] = 0.f;
#pragma unroll
        for (int ks = 0; ks < 4; ks++) {
            uint32_t bh_[10][2], bl_[10][2];
#pragma unroll
            for (int g = 0; g < 5; g++) {
                uint32_t so = ASWZ(rb + g * 16 + lrow, ks * 2 + lhalf);
                uint32_t t0, t1, t2, t3;
                ldsm4(t0, t1, t2, t3, uRh + so);
                bh_[2 * g][0] = t0; bh_[2 * g][1] = t2;
                bh_[2 * g + 1][0] = t1; bh_[2 * g + 1][1] = t3;
                ldsm4(t0, t1, t2, t3, uRl + so);
                bl_[2 * g][0] = t0; bl_[2 * g][1] = t2;
                bl_[2 * g + 1][0] = t1; bl_[2 * g + 1][1] = t3;
            }
#pragma unroll
            for (int f = 0; f < 10; f++) {
                mma16816(bd[f], qrh[ks], bh_[f]);
                mma16816(bd[f], qrh[ks], bl_[f]);
                mma16816(bd[f], qrl[ks], bh_[f]);
            }
        }
        __syncwarp();
#pragma unroll
        for (int f = 0; f < 10; f++) {
            int col = rb + f * 8 + q4 * 2;
            *(float2*)(sm + ((w * 16 + g8) * 128 + col) * 4)     = make_float2(bd[f][0], bd[f][1]);
            *(float2*)(sm + ((w * 16 + g8 + 8) * 128 + col) * 4) = make_float2(bd[f][2], bd[f][3]);
        }
        __syncwarp();

        cp_wait1();
        __syncthreads();

        // AC GEMM
        float acc[8][4];
#pragma unroll
        for (int f = 0; f < 8; f++)
#pragma unroll
            for (int e = 0; e < 4; e++) acc[f][e] = 0.f;
#pragma unroll
        for (int ks = 0; ks < 4; ks++) {
            uint32_t kh_[8][2], kl_[8][2];
#pragma unroll
            for (int g = 0; g < 4; g++) {
                uint32_t so = ASWZ(g * 16 + lrow, ks * 2 + lhalf);
                uint32_t t0, t1, t2, t3;
                ldsm4(t0, t1, t2, t3, uKh + so);
                kh_[2 * g][0] = t0; kh_[2 * g][1] = t2;
                kh_[2 * g + 1][0] = t1; kh_[2 * g + 1][1] = t3;
                ldsm4(t0, t1, t2, t3, uKl + so);
                kl_[2 * g][0] = t0; kl_[2 * g][1] = t2;
                kl_[2 * g + 1][0] = t1; kl_[2 * g + 1][1] = t3;
            }
#pragma unroll
            for (int f = 0; f < 8; f++) {
                mma16816(acc[f], qwh[ks], kh_[f]);
                mma16816(acc[f], qwh[ks], kl_[f]);
                mma16816(acc[f], qwl[ks], kh_[f]);
            }
        }

        // softmax on fragments
        const bool diag = (jt == it);
        float mx0 = -1e30f, mx1 = -1e30f;
#pragma unroll
        for (int f = 0; f < 8; f++) {
#pragma unroll
            for (int e = 0; e < 4; e++) {
                int jl = f * 8 + q4 * 2 + (e & 1);
                int il = (e < 2) ? il0 : il1;
                float sv = (acc[f][e] + bdp[il * 128 + (jl - il + 63)]) * ATT_SCALE;
                if (diag && jl > il) sv = -1e30f;
                acc[f][e] = sv;
            }
            mx0 = fmaxf(mx0, fmaxf(acc[f][0], acc[f][1]));
            mx1 = fmaxf(mx1, fmaxf(acc[f][2], acc[f][3]));
        }
        mx0 = fmaxf(mx0, __shfl_xor_sync(0xffffffffu, mx0, 1));
        mx0 = fmaxf(mx0, __shfl_xor_sync(0xffffffffu, mx0, 2));
        mx1 = fmaxf(mx1, __shfl_xor_sync(0xffffffffu, mx1, 1));
        mx1 = fmaxf(mx1, __shfl_xor_sync(0xffffffffu, mx1, 2));
        float mn0 = fmaxf(m0, mx0), mn1 = fmaxf(m1, mx1);
        float al0 = __expf(m0 - mn0), al1 = __expf(m1 - mn1);
        m0 = mn0; m1 = mn1;

        float rs0 = 0.f, rs1 = 0.f;
        uint32_t pah[4][4], pal[4][4];
#pragma unroll
        for (int f = 0; f < 8; f++) {
            float p0 = __expf(acc[f][0] - mn0), p1 = __expf(acc[f][1] - mn0);
            float p2 = __expf(acc[f][2] - mn1), p3 = __expf(acc[f][3] - mn1);
            rs0 += p0 + p1; rs1 += p2 + p3;
            __nv_bfloat16 h0 = __float2bfloat16(p0), h1 = __float2bfloat16(p1);
            __nv_bfloat16 h2 = __float2bfloat16(p2), h3 = __float2bfloat16(p3);
            uint32_t uh01, uh23, ul01, ul23;
            *(__nv_bfloat162*)&uh01 = __halves2bfloat162(h0, h1);
            *(__nv_bfloat162*)&uh23 = __halves2bfloat162(h2, h3);
            ul01 = packbf(p0 - __bfloat162float(h0), p1 - __bfloat162float(h1));
            ul23 = packbf(p2 - __bfloat162float(h2), p3 - __bfloat162float(h3));
            int kb = f >> 1;
            if ((f & 1) == 0) { pah[kb][0] = uh01; pah[kb][1] = uh23;
                                pal[kb][0] = ul01; pal[kb][1] = ul23; }
            else              { pah[kb][2] = uh01; pah[kb][3] = uh23;
                                pal[kb][2] = ul01; pal[kb][3] = ul23; }
        }
        rs0 += __shfl_xor_sync(0xffffffffu, rs0, 1);
        rs0 += __shfl_xor_sync(0xffffffffu, rs0, 2);
        rs1 += __shfl_xor_sync(0xffffffffu, rs1, 1);
        rs1 += __shfl_xor_sync(0xffffffffu, rs1, 2);
        l0 = l0 * al0 + rs0;
        l1 = l1 * al1 + rs1;
#pragma unroll
        for (int f = 0; f < 8; f++) {
            oacc[f][0] *= al0; oacc[f][1] *= al0;
            oacc[f][2] *= al1; oacc[f][3] *= al1;
        }

        cp_wait0();
        __syncthreads();

        // PV
#pragma unroll
        for (int kb = 0; kb < 4; kb++) {
            uint32_t vh_[8][2], vl_[8][2];
#pragma unroll
            for (int g = 0; g < 4; g++) {
                uint32_t so = ASWZ(kb * 16 + lrow, g * 2 + lhalf);
                uint32_t t0, t1, t2, t3;
                ldsm4t(t0, t1, t2, t3, uVh + so);
                vh_[2 * g][0] = t0; vh_[2 * g][1] = t1;
                vh_[2 * g + 1][0] = t2; vh_[2 * g + 1][1] = t3;
                ldsm4t(t0, t1, t2, t3, uVl + so);
                vl_[2 * g][0] = t0; vl_[2 * g][1] = t1;
                vl_[2 * g + 1][0] = t2; vl_[2 * g + 1][1] = t3;
            }
#pragma unroll
            for (int f = 0; f < 8; f++) {
                mma16816(oacc[f], pah[kb], vh_[f]);
                mma16816(oacc[f], pal[kb], vh_[f]);
                mma16816(oacc[f], pah[kb], vl_[f]);
            }
        }
        __syncthreads();
    }

    // epilogue: split-store directly into vec_hi/vec_lo
    float inv0 = 1.f / l0, inv1 = 1.f / l1;
    int gi0 = i0 + il0, gi1 = i0 + il1;
#pragma unroll
    for (int f = 0; f < 8; f++) {
        int d = f * 8 + q4 * 2;
        size_t o0 = ((size_t)gi0 * BSZ + b) * HD + n * 64 + d;
        size_t o1 = ((size_t)gi1 * BSZ + b) * HD + n * 64 + d;
        split2(g_vec_hi + o0, g_vec_lo + o0, oacc[f][0] * inv0, oacc[f][1] * inv0);
        split2(g_vec_hi + o1, g_vec_lo + o1, oacc[f][2] * inv1, oacc[f][3] * inv1);
    }
}

// ---------------- residual + LayerNorm ----------------
__global__ __launch_bounds__(256) void ln_kernel(
    const float* __restrict__ w, const float* __restrict__ ao,
    const float* __restrict__ g, const float* __restrict__ bb,
    float* __restrict__ out)
{
    __shared__ float red[8];
    __shared__ float s_mu, s_rstd;
    const int row = blockIdx.x;
    const int tid = threadIdx.x;
    const int lane = tid & 31, wid = tid >> 5;
    const size_t base = (size_t)row * DM + tid * 4;

    float4 wv = *(const float4*)(w + base);
    float4 av = *(const float4*)(ao + base);
    float x0 = wv.x + av.x, x1 = wv.y + av.y, x2 = wv.z + av.z, x3 = wv.w + av.w;

    float s = x0 + x1 + x2 + x3;
#pragma unroll
    for (int o = 16; o >= 1; o >>= 1) s += __shfl_xor_sync(0xffffffffu, s, o);
    if (lane == 0) red[wid] = s;
    __syncthreads();
    if (tid == 0) {
        float t = 0.f;
#pragma unroll
        for (int i = 0; i < 8; i++) t += red[i];
        s_mu = t * (1.0f / DM);
    }
    __syncthreads();
    const float mu = s_mu;

    float d0 = x0 - mu, d1 = x1 - mu, d2 = x2 - mu, d3 = x3 - mu;
    float ss = d0 * d0 + d1 * d1 + d2 * d2 + d3 * d3;
#pragma unroll
    for (int o = 16; o >= 1; o >>= 1) ss += __shfl_xor_sync(0xffffffffu, ss, o);
    if (lane == 0) red[wid] = ss;
    __syncthreads();
    if (tid == 0) {
        float t = 0.f;
#pragma unroll
        for (int i = 0; i < 8; i++) t += red[i];
        s_rstd = rsqrtf(t * (1.0f / DM) + 1e-5f);
    }
    __syncthreads();
    const float rstd = s_rstd;

    float4 gv = *(const float4*)(g + tid * 4);
    float4 bv = *(const float4*)(bb + tid * 4);
    float4 o4;
    o4.x = d0 * rstd * gv.x + bv.x;
    o4.y = d1 * rstd * gv.y + bv.y;
    o4.z = d2 * rstd * gv.z + bv.z;
    o4.w = d3 * rstd * gv.w + bv.w;
    *(float4*)(out + base) = o4;
}

// ---------------- launch ----------------
extern "C" void kernel_launch(void* const* d_in, const int* in_sizes, int n_in,
                              void* d_out, int out_size)
{
    (void)in_sizes; (void)n_in; (void)out_size;
    const float* w     = (const float*)d_in[0];
    const float* r     = (const float*)d_in[1];
    const float* rwb   = (const float*)d_in[2];
    const float* rrb   = (const float*)d_in[3];
    const float* qkv_w = (const float*)d_in[4];
    const float* qkv_b = (const float*)d_in[5];
    const float* rk_w  = (const float*)d_in[6];
    const float* rk_b  = (const float*)d_in[7];
    const float* o_w   = (const float*)d_in[8];
    const float* o_b   = (const float*)d_in[9];
    const float* ln_g  = (const float*)d_in[10];
    const float* ln_b  = (const float*)d_in[11];
    float* out = (float*)d_out;

    float* ao;
    cudaGetSymbolAddress((void**)&ao, g_ao);

    cudaFuncSetAttribute(gemm_qkv_rk_kernel, cudaFuncAttributeMaxDynamicSharedMemorySize, GSMEM);
    cudaFuncSetAttribute(gemm_out_kernel, cudaFuncAttributeMaxDynamicSharedMemorySize, GSMEM);
    cudaFuncSetAttribute(attn_mma_kernel, cudaFuncAttributeMaxDynamicSharedMemorySize, ATTM_SMEM);

    // 1) all input conversions in one launch
    prep_kernel<<<PREP_BLOCKS, 256>>>(w, r, qkv_w, rk_w, o_w);

    // 2) QKV + rk GEMMs in one launch (rk rides the QKV tail wave)
    gemm_qkv_rk_kernel<<<QKV_CTAS + 64, 256, GSMEM>>>(qkv_b, rk_b, rwb, rrb);

    // 3) fused MMA rel-attention (longest CTAs first)
    attn_mma_kernel<<<dim3(QL / 64, NH, BSZ), 128, ATTM_SMEM>>>();

    // 4) out-projection
    gemm_out_kernel<<<dim3(DM / 128, NROWS / 128), 256, GSMEM>>>(o_b, ao);

    // 5) residual + LayerNorm
    ln_kernel<<<NROWS, 256>>>(w, ao, ln_g, ln_b, out);
}